// round 1
// baseline (speedup 1.0000x reference)
#include <cuda_runtime.h>
#include <math.h>

// Problem constants
#define BB 4
#define NN 2048
#define DD 1024
#define HH 8
#define HDIM 128
#define MM (BB*NN)   // 8192 rows

// Scratch (allocation-free rule: __device__ globals)
__device__ float g_q[(size_t)MM*DD];
__device__ float g_k[(size_t)MM*DD];
__device__ float g_g[(size_t)MM*DD];
__device__ float g_v[(size_t)MM*DD];
__device__ float g_att[(size_t)MM*DD];
__device__ float g_nrm[(size_t)MM*DD];

// ---------------------------------------------------------------------------
// GEMM: C[M,Nc] = epilogue( A[M,K] @ W[Nc,K]^T )
// Both operands K-contiguous (matches x @ W.T). BM=BN=128, BK=16,
// 256 threads, 8x8 micro-tile per thread.
// MODE: 0 = SiLU (q), 1 = KG (writes k=1-f to C and g=logsigmoid(f) to C2),
//       2 = identity
// ---------------------------------------------------------------------------
template<int MODE>
__global__ __launch_bounds__(256)
void gemm_kernel(const float* __restrict__ A, const float* __restrict__ W,
                 float* __restrict__ C, float* __restrict__ C2,
                 int M, int K, int Nc)
{
    __shared__ float As[16][128];
    __shared__ float Bs[16][128];

    const int bm = blockIdx.y * 128;
    const int bn = blockIdx.x * 128;
    const int t  = threadIdx.x;
    const int tx = t & 15;        // 0..15 (col group)
    const int ty = t >> 4;        // 0..15 (row group)

    float acc[8][8];
    #pragma unroll
    for (int i = 0; i < 8; i++)
        #pragma unroll
        for (int j = 0; j < 8; j++) acc[i][j] = 0.f;

    for (int k0 = 0; k0 < K; k0 += 16) {
        // Load 128x16 tiles of A and W (512 float4 each; 2 per thread)
        #pragma unroll
        for (int r = 0; r < 2; r++) {
            int idx = t + r * 256;        // 0..511
            int row = idx & 127;
            int kq  = idx >> 7;           // 0..3
            float4 va = *reinterpret_cast<const float4*>(
                &A[(size_t)(bm + row) * K + k0 + kq * 4]);
            As[kq*4+0][row] = va.x;
            As[kq*4+1][row] = va.y;
            As[kq*4+2][row] = va.z;
            As[kq*4+3][row] = va.w;
            float4 vb = *reinterpret_cast<const float4*>(
                &W[(size_t)(bn + row) * K + k0 + kq * 4]);
            Bs[kq*4+0][row] = vb.x;
            Bs[kq*4+1][row] = vb.y;
            Bs[kq*4+2][row] = vb.z;
            Bs[kq*4+3][row] = vb.w;
        }
        __syncthreads();

        #pragma unroll
        for (int kk = 0; kk < 16; kk++) {
            float a[8], b[8];
            *reinterpret_cast<float4*>(&a[0]) =
                *reinterpret_cast<const float4*>(&As[kk][ty*8]);
            *reinterpret_cast<float4*>(&a[4]) =
                *reinterpret_cast<const float4*>(&As[kk][ty*8+4]);
            *reinterpret_cast<float4*>(&b[0]) =
                *reinterpret_cast<const float4*>(&Bs[kk][tx*8]);
            *reinterpret_cast<float4*>(&b[4]) =
                *reinterpret_cast<const float4*>(&Bs[kk][tx*8+4]);
            #pragma unroll
            for (int i = 0; i < 8; i++)
                #pragma unroll
                for (int j = 0; j < 8; j++)
                    acc[i][j] = fmaf(a[i], b[j], acc[i][j]);
        }
        __syncthreads();
    }

    // Epilogue
    #pragma unroll
    for (int i = 0; i < 8; i++) {
        size_t row = (size_t)(bm + ty*8 + i);
        #pragma unroll
        for (int j = 0; j < 8; j++) {
            int col = bn + tx*8 + j;
            float z = acc[i][j];
            if (MODE == 0) {
                // SiLU
                float s = 1.f / (1.f + __expf(-z));
                C[row * Nc + col] = z * s;
            } else if (MODE == 1) {
                // f = sigmoid(z); k = 1-f; g = log_sigmoid(f) = -log1p(exp(-f))
                float f = 1.f / (1.f + __expf(-z));
                C [row * Nc + col] = 1.f - f;
                C2[row * Nc + col] = -log1pf(__expf(-f));
            } else {
                C[row * Nc + col] = z;
            }
        }
    }
}

// ---------------------------------------------------------------------------
// GLA scan. One block per (b,h). 128 threads; thread tid owns output column
// dv = tid and keeps the full S[:,dv] column (128 floats) in registers.
// Per step: S[dk] = exp(g[dk])*S[dk] + k[dk]*v[dv]; o[dv] = sum_dk q[dk]*S[dk]
// q/k/exp(g) are broadcast from shared via LDS128 (same address all lanes).
// ---------------------------------------------------------------------------
__global__ __launch_bounds__(128)
void scan_kernel(const float* __restrict__ Q, const float* __restrict__ Kk,
                 const float* __restrict__ G, const float* __restrict__ V,
                 float* __restrict__ O)
{
    __shared__ float qs[128], ks[128], es[128];
    const int bh  = blockIdx.x;     // 0..31
    const int b   = bh / HH;
    const int h   = bh % HH;
    const int tid = threadIdx.x;    // dv

    const size_t base = (size_t)b * NN * DD + (size_t)h * HDIM;

    float S[128];
    #pragma unroll
    for (int i = 0; i < 128; i++) S[i] = 0.f;

    for (int tstep = 0; tstep < NN; tstep++) {
        size_t off = base + (size_t)tstep * DD;
        float qv = Q [off + tid];
        float kv = Kk[off + tid];
        float gv = G [off + tid];
        float vv = V [off + tid];
        qs[tid] = qv;
        ks[tid] = kv;
        es[tid] = __expf(gv);
        __syncthreads();

        const float4* q4 = reinterpret_cast<const float4*>(qs);
        const float4* k4 = reinterpret_cast<const float4*>(ks);
        const float4* e4 = reinterpret_cast<const float4*>(es);

        float o0 = 0.f, o1 = 0.f, o2 = 0.f, o3 = 0.f;
        #pragma unroll
        for (int j = 0; j < 32; j++) {
            float4 qa = q4[j], ka = k4[j], ea = e4[j];
            float s;
            s = fmaf(ea.x, S[4*j+0], ka.x * vv); S[4*j+0] = s; o0 = fmaf(qa.x, s, o0);
            s = fmaf(ea.y, S[4*j+1], ka.y * vv); S[4*j+1] = s; o1 = fmaf(qa.y, s, o1);
            s = fmaf(ea.z, S[4*j+2], ka.z * vv); S[4*j+2] = s; o2 = fmaf(qa.z, s, o2);
            s = fmaf(ea.w, S[4*j+3], ka.w * vv); S[4*j+3] = s; o3 = fmaf(qa.w, s, o3);
        }
        O[off + tid] = (o0 + o1) + (o2 + o3);
        __syncthreads();
    }
}

// ---------------------------------------------------------------------------
// RMSNorm over last dim (1024). One block per row, 256 threads x 4 elems.
// ---------------------------------------------------------------------------
__global__ __launch_bounds__(256)
void rmsnorm_kernel(const float* __restrict__ X, const float* __restrict__ w,
                    float* __restrict__ Y)
{
    __shared__ float red[8];
    const int row = blockIdx.x;
    const int t = threadIdx.x;
    const float* xr = X + (size_t)row * DD;

    float4 xv = *reinterpret_cast<const float4*>(&xr[t * 4]);
    float ss = xv.x*xv.x + xv.y*xv.y + xv.z*xv.z + xv.w*xv.w;
    #pragma unroll
    for (int o = 16; o; o >>= 1) ss += __shfl_xor_sync(0xffffffffu, ss, o);
    if ((t & 31) == 0) red[t >> 5] = ss;
    __syncthreads();
    if (t < 8) {
        float x = red[t];
        #pragma unroll
        for (int o = 4; o; o >>= 1) x += __shfl_xor_sync(0xffu, x, o);
        if (t == 0) red[0] = x;
    }
    __syncthreads();
    float inv = rsqrtf(red[0] * (1.f / DD) + 1e-6f);

    float4 wv = *reinterpret_cast<const float4*>(&w[t * 4]);
    float4 ov;
    ov.x = xv.x * inv * wv.x;
    ov.y = xv.y * inv * wv.y;
    ov.z = xv.z * inv * wv.z;
    ov.w = xv.w * inv * wv.w;
    *reinterpret_cast<float4*>(&Y[(size_t)row * DD + t * 4]) = ov;
}

// ---------------------------------------------------------------------------
extern "C" void kernel_launch(void* const* d_in, const int* in_sizes, int n_in,
                              void* d_out, int out_size)
{
    const float* x      = (const float*)d_in[0];
    const float* Wq     = (const float*)d_in[1];
    const float* Wk     = (const float*)d_in[2];
    const float* Wv     = (const float*)d_in[3];
    const float* Wo     = (const float*)d_in[4];
    const float* norm_w = (const float*)d_in[5];
    float* out = (float*)d_out;

    float *pq, *pk, *pg, *pv, *patt, *pnrm;
    cudaGetSymbolAddress((void**)&pq,   g_q);
    cudaGetSymbolAddress((void**)&pk,   g_k);
    cudaGetSymbolAddress((void**)&pg,   g_g);
    cudaGetSymbolAddress((void**)&pv,   g_v);
    cudaGetSymbolAddress((void**)&patt, g_att);
    cudaGetSymbolAddress((void**)&pnrm, g_nrm);

    dim3 gemm_grid(DD / 128, MM / 128);   // (8, 64)
    dim3 gemm_blk(256);

    // q = silu(x @ Wq^T)
    gemm_kernel<0><<<gemm_grid, gemm_blk>>>(x, Wq, pq, nullptr, MM, DD, DD);
    // f = sigmoid(x @ Wk^T); k = 1-f; g = logsigmoid(f)
    gemm_kernel<1><<<gemm_grid, gemm_blk>>>(x, Wk, pk, pg, MM, DD, DD);
    // v = x @ Wv^T
    gemm_kernel<2><<<gemm_grid, gemm_blk>>>(x, Wv, pv, nullptr, MM, DD, DD);

    // GLA scan (one block per (b,h))
    scan_kernel<<<BB * HH, 128>>>(pq, pk, pg, pv, patt);

    // RMSNorm
    rmsnorm_kernel<<<MM, 256>>>(patt, norm_w, pnrm);

    // out = normed @ Wo^T
    gemm_kernel<2><<<gemm_grid, gemm_blk>>>(pnrm, Wo, out, nullptr, MM, DD, DD);
}

// round 2
// speedup vs baseline: 2.5253x; 2.5253x over previous
#include <cuda_runtime.h>
#include <math.h>

// Problem constants
#define BB 4
#define NN 2048
#define DD 1024
#define HH 8
#define HDIM 128
#define MM (BB*NN)   // 8192 rows

// Scratch (allocation-free rule: __device__ globals)
__device__ float g_q[(size_t)MM*DD];
__device__ float g_k[(size_t)MM*DD];
__device__ float g_g[(size_t)MM*DD];
__device__ float g_v[(size_t)MM*DD];
__device__ float g_att[(size_t)MM*DD];
__device__ float g_nrm[(size_t)MM*DD];

// ---------------------------------------------------------------------------
// tf32 helpers
// ---------------------------------------------------------------------------
__device__ __forceinline__ unsigned f2tf32(float f) {
    unsigned r;
    asm("cvt.rna.tf32.f32 %0, %1;" : "=r"(r) : "f"(f));
    return r;
}

__device__ __forceinline__ void mma_tf32(float c[4], const unsigned a[4],
                                         unsigned b0, unsigned b1) {
    asm volatile(
        "mma.sync.aligned.m16n8k8.row.col.f32.tf32.tf32.f32 "
        "{%0,%1,%2,%3},{%4,%5,%6,%7},{%8,%9},{%0,%1,%2,%3};"
        : "+f"(c[0]), "+f"(c[1]), "+f"(c[2]), "+f"(c[3])
        : "r"(a[0]), "r"(a[1]), "r"(a[2]), "r"(a[3]), "r"(b0), "r"(b1));
}

// ---------------------------------------------------------------------------
// Tensor-core GEMM: C[M,Nc] = epilogue( A[M,K] @ W[Nc,K]^T ), tf32 inputs,
// fp32 accum. BM=BN=128, BK=32, 256 threads (8 warps, 4x2), warp tile 32x64.
// MODE: 0 = SiLU, 1 = KG (k=1-f -> C, g=logsigmoid(f) -> C2), 2 = identity
// ---------------------------------------------------------------------------
template<int MODE>
__global__ __launch_bounds__(256)
void gemm_tc_kernel(const float* __restrict__ A, const float* __restrict__ W,
                    float* __restrict__ C, float* __restrict__ C2,
                    int M, int K, int Nc)
{
    // stride 36 => frag loads (4*qrow + qcol) are bank-conflict-free
    __shared__ unsigned As[128][36];
    __shared__ unsigned Bs[128][36];

    const int bm = blockIdx.y * 128;
    const int bn = blockIdx.x * 128;
    const int t  = threadIdx.x;
    const int warp = t >> 5, lane = t & 31;
    const int wm = (warp >> 1) * 32;   // warp row offset within tile
    const int wn = (warp & 1) * 64;    // warp col offset within tile
    const int qrow = lane >> 2;        // 0..7
    const int qcol = lane & 3;         // 0..3

    float acc[2][8][4];
    #pragma unroll
    for (int mt = 0; mt < 2; mt++)
        #pragma unroll
        for (int nt = 0; nt < 8; nt++)
            #pragma unroll
            for (int i = 0; i < 4; i++) acc[mt][nt][i] = 0.f;

    float4 ag[4], bg[4];
    // preload k0 = 0
    #pragma unroll
    for (int r = 0; r < 4; r++) {
        int idx = t + r * 256;       // 0..1023
        int row = idx >> 3;          // 0..127
        int kq  = idx & 7;           // 0..7
        ag[r] = *reinterpret_cast<const float4*>(&A[(size_t)(bm + row) * K + kq * 4]);
        bg[r] = *reinterpret_cast<const float4*>(&W[(size_t)(bn + row) * K + kq * 4]);
    }

    for (int k0 = 0; k0 < K; k0 += 32) {
        if (k0) __syncthreads();   // smem reads from previous iter must be done

        #pragma unroll
        for (int r = 0; r < 4; r++) {
            int idx = t + r * 256;
            int row = idx >> 3;
            int kq  = idx & 7;
            As[row][kq*4+0] = f2tf32(ag[r].x);
            As[row][kq*4+1] = f2tf32(ag[r].y);
            As[row][kq*4+2] = f2tf32(ag[r].z);
            As[row][kq*4+3] = f2tf32(ag[r].w);
            Bs[row][kq*4+0] = f2tf32(bg[r].x);
            Bs[row][kq*4+1] = f2tf32(bg[r].y);
            Bs[row][kq*4+2] = f2tf32(bg[r].z);
            Bs[row][kq*4+3] = f2tf32(bg[r].w);
        }
        if (k0 + 32 < K) {
            #pragma unroll
            for (int r = 0; r < 4; r++) {
                int idx = t + r * 256;
                int row = idx >> 3;
                int kq  = idx & 7;
                ag[r] = *reinterpret_cast<const float4*>(
                    &A[(size_t)(bm + row) * K + k0 + 32 + kq * 4]);
                bg[r] = *reinterpret_cast<const float4*>(
                    &W[(size_t)(bn + row) * K + k0 + 32 + kq * 4]);
            }
        }
        __syncthreads();

        #pragma unroll
        for (int ks = 0; ks < 4; ks++) {
            const int kk = ks * 8;
            unsigned a[2][4];
            #pragma unroll
            for (int mt = 0; mt < 2; mt++) {
                int r0 = wm + mt * 16 + qrow;
                a[mt][0] = As[r0    ][kk + qcol];
                a[mt][1] = As[r0 + 8][kk + qcol];
                a[mt][2] = As[r0    ][kk + qcol + 4];
                a[mt][3] = As[r0 + 8][kk + qcol + 4];
            }
            #pragma unroll
            for (int nt = 0; nt < 8; nt++) {
                int c0 = wn + nt * 8 + qrow;
                unsigned b0 = Bs[c0][kk + qcol];
                unsigned b1 = Bs[c0][kk + qcol + 4];
                mma_tf32(acc[0][nt], a[0], b0, b1);
                mma_tf32(acc[1][nt], a[1], b0, b1);
            }
        }
    }

    // Epilogue: thread's frag -> (row, col) = c0/c1 at (r, c), c2/c3 at (r+8, c)
    #pragma unroll
    for (int mt = 0; mt < 2; mt++) {
        #pragma unroll
        for (int nt = 0; nt < 8; nt++) {
            int row = bm + wm + mt * 16 + qrow;
            int col = bn + wn + nt * 8 + qcol * 2;
            #pragma unroll
            for (int half = 0; half < 2; half++) {
                int r = row + half * 8;
                float z0 = acc[mt][nt][half * 2 + 0];
                float z1 = acc[mt][nt][half * 2 + 1];
                if (MODE == 0) {
                    float s0 = 1.f / (1.f + __expf(-z0));
                    float s1 = 1.f / (1.f + __expf(-z1));
                    float2 o = make_float2(z0 * s0, z1 * s1);
                    *reinterpret_cast<float2*>(&C[(size_t)r * Nc + col]) = o;
                } else if (MODE == 1) {
                    float f0 = 1.f / (1.f + __expf(-z0));
                    float f1 = 1.f / (1.f + __expf(-z1));
                    float2 kk2 = make_float2(1.f - f0, 1.f - f1);
                    float2 gg2 = make_float2(-log1pf(__expf(-f0)),
                                             -log1pf(__expf(-f1)));
                    *reinterpret_cast<float2*>(&C [(size_t)r * Nc + col]) = kk2;
                    *reinterpret_cast<float2*>(&C2[(size_t)r * Nc + col]) = gg2;
                } else {
                    float2 o = make_float2(z0, z1);
                    *reinterpret_cast<float2*>(&C[(size_t)r * Nc + col]) = o;
                }
            }
        }
    }
}

// ---------------------------------------------------------------------------
// GLA scan v2. Grid (32, 4): blockIdx.x = (b,h), blockIdx.y = dv-block (32
// cols). 128 threads: thread = (dv_local = tid>>2, dkq = tid&3). Each thread
// owns S for 32 dk values (float4 groups j*4+dkq, j=0..7) and one dv column.
// Per step: S = exp(g)*S + k*v; o = sum_dk q*S, reduced over 4 lanes by shfl.
// Double-buffered shared staging, one sync per step.
// ---------------------------------------------------------------------------
__global__ __launch_bounds__(128)
void scan_kernel(const float* __restrict__ Q, const float* __restrict__ Kk,
                 const float* __restrict__ G, const float* __restrict__ V,
                 float* __restrict__ O)
{
    __shared__ __align__(16) float qs[2][128];
    __shared__ __align__(16) float ksh[2][128];
    __shared__ __align__(16) float es[2][128];

    const int bh  = blockIdx.x;        // 0..31
    const int dvb = blockIdx.y;        // 0..3
    const int b   = bh >> 3;
    const int h   = bh & 7;
    const int tid = threadIdx.x;
    const int dv_local = tid >> 2;     // 0..31
    const int dkq      = tid & 3;      // 0..3
    const int vcol     = dvb * 32 + dv_local;

    const size_t base = (size_t)b * NN * DD + (size_t)h * HDIM;

    float S[32];
    #pragma unroll
    for (int i = 0; i < 32; i++) S[i] = 0.f;

    size_t off = base;
    float qr = Q [off + tid];
    float kr = Kk[off + tid];
    float gr = G [off + tid];
    float vr = V [off + vcol];

    #pragma unroll 1
    for (int tstep = 0; tstep < NN; tstep++) {
        const int bufi = tstep & 1;
        qs [bufi][tid] = qr;
        ksh[bufi][tid] = kr;
        es [bufi][tid] = __expf(gr);
        const float vv = vr;

        const size_t noff = off + DD;
        if (tstep + 1 < NN) {
            qr = Q [noff + tid];
            kr = Kk[noff + tid];
            gr = G [noff + tid];
            vr = V [noff + vcol];
        }
        __syncthreads();

        const float4* q4 = reinterpret_cast<const float4*>(qs [bufi]);
        const float4* k4 = reinterpret_cast<const float4*>(ksh[bufi]);
        const float4* e4 = reinterpret_cast<const float4*>(es [bufi]);

        float o = 0.f;
        #pragma unroll
        for (int j = 0; j < 8; j++) {
            const int fi = j * 4 + dkq;   // float4 index: 4 consecutive across dkq
            float4 qa = q4[fi], ka = k4[fi], ea = e4[fi];
            float s;
            s = fmaf(ea.x, S[4*j+0], ka.x * vv); S[4*j+0] = s; o = fmaf(qa.x, s, o);
            s = fmaf(ea.y, S[4*j+1], ka.y * vv); S[4*j+1] = s; o = fmaf(qa.y, s, o);
            s = fmaf(ea.z, S[4*j+2], ka.z * vv); S[4*j+2] = s; o = fmaf(qa.z, s, o);
            s = fmaf(ea.w, S[4*j+3], ka.w * vv); S[4*j+3] = s; o = fmaf(qa.w, s, o);
        }
        // reduce partial o across the 4 dkq lanes (adjacent in warp)
        o += __shfl_xor_sync(0xffffffffu, o, 1);
        o += __shfl_xor_sync(0xffffffffu, o, 2);
        if (dkq == 0) O[off + vcol] = o;

        off = noff;
    }
}

// ---------------------------------------------------------------------------
// RMSNorm over last dim (1024). One block per row, 256 threads x 4 elems.
// ---------------------------------------------------------------------------
__global__ __launch_bounds__(256)
void rmsnorm_kernel(const float* __restrict__ X, const float* __restrict__ w,
                    float* __restrict__ Y)
{
    __shared__ float red[8];
    const int row = blockIdx.x;
    const int t = threadIdx.x;
    const float* xr = X + (size_t)row * DD;

    float4 xv = *reinterpret_cast<const float4*>(&xr[t * 4]);
    float ss = xv.x*xv.x + xv.y*xv.y + xv.z*xv.z + xv.w*xv.w;
    #pragma unroll
    for (int o = 16; o; o >>= 1) ss += __shfl_xor_sync(0xffffffffu, ss, o);
    if ((t & 31) == 0) red[t >> 5] = ss;
    __syncthreads();
    if (t < 8) {
        float x = red[t];
        #pragma unroll
        for (int o = 4; o; o >>= 1) x += __shfl_xor_sync(0xffu, x, o);
        if (t == 0) red[0] = x;
    }
    __syncthreads();
    float inv = rsqrtf(red[0] * (1.f / DD) + 1e-6f);

    float4 wv = *reinterpret_cast<const float4*>(&w[t * 4]);
    float4 ov;
    ov.x = xv.x * inv * wv.x;
    ov.y = xv.y * inv * wv.y;
    ov.z = xv.z * inv * wv.z;
    ov.w = xv.w * inv * wv.w;
    *reinterpret_cast<float4*>(&Y[(size_t)row * DD + t * 4]) = ov;
}

// ---------------------------------------------------------------------------
extern "C" void kernel_launch(void* const* d_in, const int* in_sizes, int n_in,
                              void* d_out, int out_size)
{
    const float* x      = (const float*)d_in[0];
    const float* Wq     = (const float*)d_in[1];
    const float* Wk     = (const float*)d_in[2];
    const float* Wv     = (const float*)d_in[3];
    const float* Wo     = (const float*)d_in[4];
    const float* norm_w = (const float*)d_in[5];
    float* out = (float*)d_out;

    float *pq, *pk, *pg, *pv, *patt, *pnrm;
    cudaGetSymbolAddress((void**)&pq,   g_q);
    cudaGetSymbolAddress((void**)&pk,   g_k);
    cudaGetSymbolAddress((void**)&pg,   g_g);
    cudaGetSymbolAddress((void**)&pv,   g_v);
    cudaGetSymbolAddress((void**)&patt, g_att);
    cudaGetSymbolAddress((void**)&pnrm, g_nrm);

    dim3 gemm_grid(DD / 128, MM / 128);   // (8, 64)
    dim3 gemm_blk(256);

    // q = silu(x @ Wq^T)
    gemm_tc_kernel<0><<<gemm_grid, gemm_blk>>>(x, Wq, pq, nullptr, MM, DD, DD);
    // f = sigmoid(x @ Wk^T); k = 1-f; g = logsigmoid(f)
    gemm_tc_kernel<1><<<gemm_grid, gemm_blk>>>(x, Wk, pk, pg, MM, DD, DD);
    // v = x @ Wv^T
    gemm_tc_kernel<2><<<gemm_grid, gemm_blk>>>(x, Wv, pv, nullptr, MM, DD, DD);

    // GLA scan: 32 (b,h) pairs x 4 dv-blocks = 128 blocks
    scan_kernel<<<dim3(BB * HH, 4), 128>>>(pq, pk, pg, pv, patt);

    // RMSNorm
    rmsnorm_kernel<<<MM, 256>>>(patt, norm_w, pnrm);

    // out = normed @ Wo^T
    gemm_tc_kernel<2><<<gemm_grid, gemm_blk>>>(pnrm, Wo, out, nullptr, MM, DD, DD);
}

// round 3
// speedup vs baseline: 2.5514x; 1.0103x over previous
#include <cuda_runtime.h>
#include <math.h>

// Problem constants
#define BB 4
#define NN 2048
#define DD 1024
#define HH 8
#define HDIM 128
#define MM (BB*NN)   // 8192 rows

// Scratch (allocation-free rule: __device__ globals)
__device__ float g_q[(size_t)MM*DD];
__device__ float g_k[(size_t)MM*DD];
__device__ float g_g[(size_t)MM*DD];
__device__ float g_v[(size_t)MM*DD];
__device__ float g_p0[(size_t)MM*DD];   // partial scan outputs per dk-block
__device__ float g_p1[(size_t)MM*DD];
__device__ float g_p2[(size_t)MM*DD];
__device__ float g_p3[(size_t)MM*DD];
__device__ float g_nrm[(size_t)MM*DD];

// ---------------------------------------------------------------------------
// tf32 helpers
// ---------------------------------------------------------------------------
__device__ __forceinline__ unsigned f2tf32(float f) {
    unsigned r;
    asm("cvt.rna.tf32.f32 %0, %1;" : "=r"(r) : "f"(f));
    return r;
}

__device__ __forceinline__ void mma_tf32(float c[4], const unsigned a[4],
                                         unsigned b0, unsigned b1) {
    asm volatile(
        "mma.sync.aligned.m16n8k8.row.col.f32.tf32.tf32.f32 "
        "{%0,%1,%2,%3},{%4,%5,%6,%7},{%8,%9},{%0,%1,%2,%3};"
        : "+f"(c[0]), "+f"(c[1]), "+f"(c[2]), "+f"(c[3])
        : "r"(a[0]), "r"(a[1]), "r"(a[2]), "r"(a[3]), "r"(b0), "r"(b1));
}

// ---------------------------------------------------------------------------
// Tensor-core GEMM: C[M,Nc] = epilogue( A[M,K] @ W[Nc,K]^T ), tf32 inputs,
// fp32 accum. BM=BN=128, BK=32, 256 threads (8 warps, 4x2), warp tile 32x64.
// MODE: 0 = SiLU, 1 = KG (k=1-f -> C, g=logsigmoid(f) -> C2), 2 = identity
// ---------------------------------------------------------------------------
template<int MODE>
__global__ __launch_bounds__(256)
void gemm_tc_kernel(const float* __restrict__ A, const float* __restrict__ W,
                    float* __restrict__ C, float* __restrict__ C2,
                    int M, int K, int Nc)
{
    // stride 36 => frag loads (4*qrow + qcol) are bank-conflict-free,
    // and [row][kq*4] is 16B-aligned for vector stores.
    __shared__ unsigned As[128][36];
    __shared__ unsigned Bs[128][36];

    const int bm = blockIdx.y * 128;
    const int bn = blockIdx.x * 128;
    const int t  = threadIdx.x;
    const int warp = t >> 5, lane = t & 31;
    const int wm = (warp >> 1) * 32;   // warp row offset within tile
    const int wn = (warp & 1) * 64;    // warp col offset within tile
    const int qrow = lane >> 2;        // 0..7
    const int qcol = lane & 3;         // 0..3

    float acc[2][8][4];
    #pragma unroll
    for (int mt = 0; mt < 2; mt++)
        #pragma unroll
        for (int nt = 0; nt < 8; nt++)
            #pragma unroll
            for (int i = 0; i < 4; i++) acc[mt][nt][i] = 0.f;

    float4 ag[4], bg[4];
    // preload k0 = 0
    #pragma unroll
    for (int r = 0; r < 4; r++) {
        int idx = t + r * 256;       // 0..1023
        int row = idx >> 3;          // 0..127
        int kq  = idx & 7;           // 0..7
        ag[r] = *reinterpret_cast<const float4*>(&A[(size_t)(bm + row) * K + kq * 4]);
        bg[r] = *reinterpret_cast<const float4*>(&W[(size_t)(bn + row) * K + kq * 4]);
    }

    for (int k0 = 0; k0 < K; k0 += 32) {
        if (k0) __syncthreads();   // smem reads from previous iter must be done

        #pragma unroll
        for (int r = 0; r < 4; r++) {
            int idx = t + r * 256;
            int row = idx >> 3;
            int kq  = idx & 7;
            uint4 av, bv;
            av.x = f2tf32(ag[r].x); av.y = f2tf32(ag[r].y);
            av.z = f2tf32(ag[r].z); av.w = f2tf32(ag[r].w);
            bv.x = f2tf32(bg[r].x); bv.y = f2tf32(bg[r].y);
            bv.z = f2tf32(bg[r].z); bv.w = f2tf32(bg[r].w);
            *reinterpret_cast<uint4*>(&As[row][kq*4]) = av;
            *reinterpret_cast<uint4*>(&Bs[row][kq*4]) = bv;
        }
        if (k0 + 32 < K) {
            #pragma unroll
            for (int r = 0; r < 4; r++) {
                int idx = t + r * 256;
                int row = idx >> 3;
                int kq  = idx & 7;
                ag[r] = *reinterpret_cast<const float4*>(
                    &A[(size_t)(bm + row) * K + k0 + 32 + kq * 4]);
                bg[r] = *reinterpret_cast<const float4*>(
                    &W[(size_t)(bn + row) * K + k0 + 32 + kq * 4]);
            }
        }
        __syncthreads();

        #pragma unroll
        for (int ks = 0; ks < 4; ks++) {
            const int kk = ks * 8;
            unsigned a[2][4];
            #pragma unroll
            for (int mt = 0; mt < 2; mt++) {
                int r0 = wm + mt * 16 + qrow;
                a[mt][0] = As[r0    ][kk + qcol];
                a[mt][1] = As[r0 + 8][kk + qcol];
                a[mt][2] = As[r0    ][kk + qcol + 4];
                a[mt][3] = As[r0 + 8][kk + qcol + 4];
            }
            #pragma unroll
            for (int nt = 0; nt < 8; nt++) {
                int c0 = wn + nt * 8 + qrow;
                unsigned b0 = Bs[c0][kk + qcol];
                unsigned b1 = Bs[c0][kk + qcol + 4];
                mma_tf32(acc[0][nt], a[0], b0, b1);
                mma_tf32(acc[1][nt], a[1], b0, b1);
            }
        }
    }

    // Epilogue: thread's frag -> (row, col) = c0/c1 at (r, c), c2/c3 at (r+8, c)
    #pragma unroll
    for (int mt = 0; mt < 2; mt++) {
        #pragma unroll
        for (int nt = 0; nt < 8; nt++) {
            int row = bm + wm + mt * 16 + qrow;
            int col = bn + wn + nt * 8 + qcol * 2;
            #pragma unroll
            for (int half = 0; half < 2; half++) {
                int r = row + half * 8;
                float z0 = acc[mt][nt][half * 2 + 0];
                float z1 = acc[mt][nt][half * 2 + 1];
                if (MODE == 0) {
                    float s0 = 1.f / (1.f + __expf(-z0));
                    float s1 = 1.f / (1.f + __expf(-z1));
                    float2 o = make_float2(z0 * s0, z1 * s1);
                    *reinterpret_cast<float2*>(&C[(size_t)r * Nc + col]) = o;
                } else if (MODE == 1) {
                    float f0 = 1.f / (1.f + __expf(-z0));
                    float f1 = 1.f / (1.f + __expf(-z1));
                    float2 kk2 = make_float2(1.f - f0, 1.f - f1);
                    float2 gg2 = make_float2(-log1pf(__expf(-f0)),
                                             -log1pf(__expf(-f1)));
                    *reinterpret_cast<float2*>(&C [(size_t)r * Nc + col]) = kk2;
                    *reinterpret_cast<float2*>(&C2[(size_t)r * Nc + col]) = gg2;
                } else {
                    float2 o = make_float2(z0, z1);
                    *reinterpret_cast<float2*>(&C[(size_t)r * Nc + col]) = o;
                }
            }
        }
    }
}

// ---------------------------------------------------------------------------
// GLA scan v3. Grid (32, 4, 4): x = (b,h), y = dv-block (32 cols),
// z = dk-block (32 rows). 128 threads: thread = (dv_local = tid>>2,
// dkq = tid&3). Each thread owns 8 S values (dk = dkb*32 + [dkq*8..dkq*8+7]
// as two float4 groups) for one dv column. Per step:
//   S = exp(g)*S + k*v ;  o_partial = sum_{owned dk} q*S
// o_partial reduced over the 4 dkq lanes by shfl, written to the dk-block's
// partial buffer; the 4 buffers are summed in the fused RMSNorm.
// Double-buffered shared staging, one sync per step.
// ---------------------------------------------------------------------------
__global__ __launch_bounds__(128)
void scan_kernel(const float* __restrict__ Q, const float* __restrict__ Kk,
                 const float* __restrict__ G, const float* __restrict__ V,
                 float* __restrict__ P0, float* __restrict__ P1,
                 float* __restrict__ P2, float* __restrict__ P3)
{
    __shared__ __align__(16) float qs[2][32];
    __shared__ __align__(16) float ksh[2][32];
    __shared__ __align__(16) float es[2][32];
    __shared__ __align__(16) float vs[2][32];

    const int bh  = blockIdx.x;        // 0..31
    const int dvb = blockIdx.y;        // 0..3
    const int dkb = blockIdx.z;        // 0..3
    const int b   = bh >> 3;
    const int h   = bh & 7;
    const int tid = threadIdx.x;
    const int dv_local = tid >> 2;     // 0..31
    const int dkq      = tid & 3;      // 0..3
    const int vcol     = dvb * 32 + dv_local;

    float* OP = (dkb == 0) ? P0 : (dkb == 1) ? P1 : (dkb == 2) ? P2 : P3;

    const size_t base = (size_t)b * NN * DD + (size_t)h * HDIM;

    float S[8];
    #pragma unroll
    for (int i = 0; i < 8; i++) S[i] = 0.f;

    // staging roles: tid<32 loads q/k/g for dk = dkb*32+tid; tid in [32,64)
    // loads v for dv = dvb*32 + (tid-32)
    size_t off = base;
    float r0 = 0.f, r1 = 0.f, r2 = 0.f;
    if (tid < 32) {
        r0 = Q [off + dkb*32 + tid];
        r1 = Kk[off + dkb*32 + tid];
        r2 = G [off + dkb*32 + tid];
    } else if (tid < 64) {
        r0 = V [off + dvb*32 + (tid - 32)];
    }

    #pragma unroll 1
    for (int tstep = 0; tstep < NN; tstep++) {
        const int bufi = tstep & 1;
        if (tid < 32) {
            qs [bufi][tid] = r0;
            ksh[bufi][tid] = r1;
            es [bufi][tid] = __expf(r2);
        } else if (tid < 64) {
            vs[bufi][tid - 32] = r0;
        }

        const size_t noff = off + DD;
        if (tstep + 1 < NN) {
            if (tid < 32) {
                r0 = Q [noff + dkb*32 + tid];
                r1 = Kk[noff + dkb*32 + tid];
                r2 = G [noff + dkb*32 + tid];
            } else if (tid < 64) {
                r0 = V [noff + dvb*32 + (tid - 32)];
            }
        }
        __syncthreads();

        const float4* q4 = reinterpret_cast<const float4*>(qs [bufi]);
        const float4* k4 = reinterpret_cast<const float4*>(ksh[bufi]);
        const float4* e4 = reinterpret_cast<const float4*>(es [bufi]);
        const float vv = vs[bufi][dv_local];

        float o = 0.f;
        #pragma unroll
        for (int j = 0; j < 2; j++) {
            const int fi = dkq * 2 + j;   // this thread's float4 groups
            float4 qa = q4[fi], ka = k4[fi], ea = e4[fi];
            float s;
            s = fmaf(ea.x, S[4*j+0], ka.x * vv); S[4*j+0] = s; o = fmaf(qa.x, s, o);
            s = fmaf(ea.y, S[4*j+1], ka.y * vv); S[4*j+1] = s; o = fmaf(qa.y, s, o);
            s = fmaf(ea.z, S[4*j+2], ka.z * vv); S[4*j+2] = s; o = fmaf(qa.z, s, o);
            s = fmaf(ea.w, S[4*j+3], ka.w * vv); S[4*j+3] = s; o = fmaf(qa.w, s, o);
        }
        // reduce partial o across the 4 dkq lanes (adjacent in warp)
        o += __shfl_xor_sync(0xffffffffu, o, 1);
        o += __shfl_xor_sync(0xffffffffu, o, 2);
        if (dkq == 0) OP[off + vcol] = o;

        off = noff;
    }
}

// ---------------------------------------------------------------------------
// Fused 4-way sum + RMSNorm over last dim (1024). One block per row,
// 256 threads x 4 elems.
// ---------------------------------------------------------------------------
__global__ __launch_bounds__(256)
void rmsnorm_kernel(const float* __restrict__ X0, const float* __restrict__ X1,
                    const float* __restrict__ X2, const float* __restrict__ X3,
                    const float* __restrict__ w, float* __restrict__ Y)
{
    __shared__ float red[8];
    const int row = blockIdx.x;
    const int t = threadIdx.x;
    const size_t idx = (size_t)row * DD + t * 4;

    float4 a = *reinterpret_cast<const float4*>(&X0[idx]);
    float4 bq = *reinterpret_cast<const float4*>(&X1[idx]);
    float4 c = *reinterpret_cast<const float4*>(&X2[idx]);
    float4 d = *reinterpret_cast<const float4*>(&X3[idx]);
    float4 xv;
    xv.x = (a.x + bq.x) + (c.x + d.x);
    xv.y = (a.y + bq.y) + (c.y + d.y);
    xv.z = (a.z + bq.z) + (c.z + d.z);
    xv.w = (a.w + bq.w) + (c.w + d.w);

    float ss = xv.x*xv.x + xv.y*xv.y + xv.z*xv.z + xv.w*xv.w;
    #pragma unroll
    for (int o = 16; o; o >>= 1) ss += __shfl_xor_sync(0xffffffffu, ss, o);
    if ((t & 31) == 0) red[t >> 5] = ss;
    __syncthreads();
    if (t < 8) {
        float x = red[t];
        #pragma unroll
        for (int o = 4; o; o >>= 1) x += __shfl_xor_sync(0xffu, x, o);
        if (t == 0) red[0] = x;
    }
    __syncthreads();
    float inv = rsqrtf(red[0] * (1.f / DD) + 1e-6f);

    float4 wv = *reinterpret_cast<const float4*>(&w[t * 4]);
    float4 ov;
    ov.x = xv.x * inv * wv.x;
    ov.y = xv.y * inv * wv.y;
    ov.z = xv.z * inv * wv.z;
    ov.w = xv.w * inv * wv.w;
    *reinterpret_cast<float4*>(&Y[idx]) = ov;
}

// ---------------------------------------------------------------------------
extern "C" void kernel_launch(void* const* d_in, const int* in_sizes, int n_in,
                              void* d_out, int out_size)
{
    const float* x      = (const float*)d_in[0];
    const float* Wq     = (const float*)d_in[1];
    const float* Wk     = (const float*)d_in[2];
    const float* Wv     = (const float*)d_in[3];
    const float* Wo     = (const float*)d_in[4];
    const float* norm_w = (const float*)d_in[5];
    float* out = (float*)d_out;

    float *pq, *pk, *pg, *pv, *p0, *p1, *p2, *p3, *pnrm;
    cudaGetSymbolAddress((void**)&pq,   g_q);
    cudaGetSymbolAddress((void**)&pk,   g_k);
    cudaGetSymbolAddress((void**)&pg,   g_g);
    cudaGetSymbolAddress((void**)&pv,   g_v);
    cudaGetSymbolAddress((void**)&p0,   g_p0);
    cudaGetSymbolAddress((void**)&p1,   g_p1);
    cudaGetSymbolAddress((void**)&p2,   g_p2);
    cudaGetSymbolAddress((void**)&p3,   g_p3);
    cudaGetSymbolAddress((void**)&pnrm, g_nrm);

    dim3 gemm_grid(DD / 128, MM / 128);   // (8, 64)
    dim3 gemm_blk(256);

    // q = silu(x @ Wq^T)
    gemm_tc_kernel<0><<<gemm_grid, gemm_blk>>>(x, Wq, pq, nullptr, MM, DD, DD);
    // f = sigmoid(x @ Wk^T); k = 1-f; g = logsigmoid(f)
    gemm_tc_kernel<1><<<gemm_grid, gemm_blk>>>(x, Wk, pk, pg, MM, DD, DD);
    // v = x @ Wv^T
    gemm_tc_kernel<2><<<gemm_grid, gemm_blk>>>(x, Wv, pv, nullptr, MM, DD, DD);

    // GLA scan: 32 (b,h) x 4 dv-blocks x 4 dk-blocks = 512 blocks
    scan_kernel<<<dim3(BB * HH, 4, 4), 128>>>(pq, pk, pg, pv, p0, p1, p2, p3);

    // Fused partial-sum + RMSNorm
    rmsnorm_kernel<<<MM, 256>>>(p0, p1, p2, p3, norm_w, pnrm);

    // out = normed @ Wo^T
    gemm_tc_kernel<2><<<gemm_grid, gemm_blk>>>(pnrm, Wo, out, nullptr, MM, DD, DD);
}

// round 5
// speedup vs baseline: 2.5881x; 1.0144x over previous
#include <cuda_runtime.h>
#include <math.h>
#include <stdint.h>

// Problem constants
#define BB 4
#define NN 2048
#define DD 1024
#define HH 8
#define HDIM 128
#define MM (BB*NN)   // 8192 rows

// Scratch (allocation-free rule: __device__ globals)
__device__ float g_q[(size_t)MM*DD];
__device__ float g_k[(size_t)MM*DD];
__device__ float g_g[(size_t)MM*DD];
__device__ float g_v[(size_t)MM*DD];
__device__ float g_p0[(size_t)MM*DD];   // partial scan outputs per dk-block
__device__ float g_p1[(size_t)MM*DD];
__device__ float g_p2[(size_t)MM*DD];
__device__ float g_p3[(size_t)MM*DD];
__device__ float g_nrm[(size_t)MM*DD];  // rmsnorm output, pre-rounded to tf32
__device__ float g_cx[(size_t)MM*DD];   // x pre-rounded to tf32
__device__ float g_cw[4][(size_t)DD*DD]; // weights pre-rounded to tf32

// ---------------------------------------------------------------------------
// tf32 helpers
// ---------------------------------------------------------------------------
__device__ __forceinline__ unsigned f2tf32(float f) {
    unsigned r;
    asm("cvt.rna.tf32.f32 %0, %1;" : "=r"(r) : "f"(f));
    return r;
}

__device__ __forceinline__ void mma_tf32(float c[4], const unsigned a[4],
                                         unsigned b0, unsigned b1) {
    asm volatile(
        "mma.sync.aligned.m16n8k8.row.col.f32.tf32.tf32.f32 "
        "{%0,%1,%2,%3},{%4,%5,%6,%7},{%8,%9},{%0,%1,%2,%3};"
        : "+f"(c[0]), "+f"(c[1]), "+f"(c[2]), "+f"(c[3])
        : "r"(a[0]), "r"(a[1]), "r"(a[2]), "r"(a[3]), "r"(b0), "r"(b1));
}

__device__ __forceinline__ void cp16(uint32_t dst, const void* src) {
    asm volatile("cp.async.cg.shared.global [%0], [%1], 16;"
                 :: "r"(dst), "l"(src));
}

__device__ __forceinline__ uint32_t s2u(const void* p) {
    uint32_t a;
    asm("{ .reg .u64 t; cvta.to.shared.u64 t, %1; cvt.u32.u64 %0, t; }"
        : "=r"(a) : "l"(p));
    return a;
}

// ---------------------------------------------------------------------------
// Pre-pass: round fp32 -> tf32 bit pattern (stored as fp32). Memory-bound.
// ---------------------------------------------------------------------------
__global__ __launch_bounds__(256)
void cvt_tf32_kernel(const float4* __restrict__ in, float4* __restrict__ out,
                     int n4)
{
    int i = blockIdx.x * blockDim.x + threadIdx.x;
    if (i < n4) {
        float4 v = in[i];
        v.x = __uint_as_float(f2tf32(v.x));
        v.y = __uint_as_float(f2tf32(v.y));
        v.z = __uint_as_float(f2tf32(v.z));
        v.w = __uint_as_float(f2tf32(v.w));
        out[i] = v;
    }
}

// ---------------------------------------------------------------------------
// Tensor-core GEMM: C[M,Nc] = epilogue( A[M,K] @ W[Nc,K]^T ), inputs already
// tf32-rounded. BM=BN=128, BK=32, 256 threads (8 warps, 4x2), warp tile
// 32x64. cp.async 2-stage double buffer; main loop is LDS + HMMA only.
// MODE: 0 = SiLU, 1 = KG (k=1-f -> C, g=logsigmoid(f) -> C2), 2 = identity
// ---------------------------------------------------------------------------
template<int MODE>
__global__ __launch_bounds__(256)
void gemm_tc_kernel(const float* __restrict__ A, const float* __restrict__ W,
                    float* __restrict__ C, float* __restrict__ C2)
{
    const int K = DD, Nc = DD;
    // stride 36 words: frag loads bank-conflict-free, rows 16B-aligned
    __shared__ unsigned As[2][128][36];
    __shared__ unsigned Bs[2][128][36];

    const int bm = blockIdx.y * 128;
    const int bn = blockIdx.x * 128;
    const int t  = threadIdx.x;
    const int warp = t >> 5, lane = t & 31;
    const int wm = (warp >> 1) * 32;   // warp row offset within tile
    const int wn = (warp & 1) * 64;    // warp col offset within tile
    const int qrow = lane >> 2;        // 0..7
    const int qcol = lane & 3;         // 0..3

    float acc[2][8][4];
    #pragma unroll
    for (int mt = 0; mt < 2; mt++)
        #pragma unroll
        for (int nt = 0; nt < 8; nt++)
            #pragma unroll
            for (int i = 0; i < 4; i++) acc[mt][nt][i] = 0.f;

    // per-thread cp.async pattern: 4 segments each for A and B
    int rowv[4], colv[4];
    #pragma unroll
    for (int r = 0; r < 4; r++) {
        int idx = t + r * 256;       // 0..1023
        rowv[r] = idx >> 3;          // 0..127
        colv[r] = (idx & 7) * 4;     // 0,4,..28
    }

    // prefetch chunk 0
    #pragma unroll
    for (int r = 0; r < 4; r++) {
        cp16(s2u(&As[0][rowv[r]][colv[r]]),
             &A[(size_t)(bm + rowv[r]) * K + colv[r]]);
        cp16(s2u(&Bs[0][rowv[r]][colv[r]]),
             &W[(size_t)(bn + rowv[r]) * K + colv[r]]);
    }
    asm volatile("cp.async.commit_group;" ::: "memory");

    const int NCH = K / 32;   // 32 chunks
    #pragma unroll 1
    for (int ch = 0; ch < NCH; ch++) {
        const int buf = ch & 1;
        if (ch + 1 < NCH) {
            const int k0n = (ch + 1) * 32;
            #pragma unroll
            for (int r = 0; r < 4; r++) {
                cp16(s2u(&As[buf ^ 1][rowv[r]][colv[r]]),
                     &A[(size_t)(bm + rowv[r]) * K + k0n + colv[r]]);
                cp16(s2u(&Bs[buf ^ 1][rowv[r]][colv[r]]),
                     &W[(size_t)(bn + rowv[r]) * K + k0n + colv[r]]);
            }
            asm volatile("cp.async.commit_group;" ::: "memory");
            asm volatile("cp.async.wait_group 1;" ::: "memory");
        } else {
            asm volatile("cp.async.wait_group 0;" ::: "memory");
        }
        __syncthreads();

        #pragma unroll
        for (int ks = 0; ks < 4; ks++) {
            const int kk = ks * 8;
            unsigned a[2][4];
            #pragma unroll
            for (int mt = 0; mt < 2; mt++) {
                int r0 = wm + mt * 16 + qrow;
                a[mt][0] = As[buf][r0    ][kk + qcol];
                a[mt][1] = As[buf][r0 + 8][kk + qcol];
                a[mt][2] = As[buf][r0    ][kk + qcol + 4];
                a[mt][3] = As[buf][r0 + 8][kk + qcol + 4];
            }
            #pragma unroll
            for (int nt = 0; nt < 8; nt++) {
                int c0 = wn + nt * 8 + qrow;
                unsigned b0 = Bs[buf][c0][kk + qcol];
                unsigned b1 = Bs[buf][c0][kk + qcol + 4];
                mma_tf32(acc[0][nt], a[0], b0, b1);
                mma_tf32(acc[1][nt], a[1], b0, b1);
            }
        }
        __syncthreads();   // done reading buf before it is refilled
    }

    // Epilogue: thread's frag -> (row, col) = c0/c1 at (r, c), c2/c3 at (r+8, c)
    #pragma unroll
    for (int mt = 0; mt < 2; mt++) {
        #pragma unroll
        for (int nt = 0; nt < 8; nt++) {
            int row = bm + wm + mt * 16 + qrow;
            int col = bn + wn + nt * 8 + qcol * 2;
            #pragma unroll
            for (int half = 0; half < 2; half++) {
                int r = row + half * 8;
                float z0 = acc[mt][nt][half * 2 + 0];
                float z1 = acc[mt][nt][half * 2 + 1];
                if (MODE == 0) {
                    float s0 = 1.f / (1.f + __expf(-z0));
                    float s1 = 1.f / (1.f + __expf(-z1));
                    float2 o = make_float2(z0 * s0, z1 * s1);
                    *reinterpret_cast<float2*>(&C[(size_t)r * Nc + col]) = o;
                } else if (MODE == 1) {
                    float f0 = 1.f / (1.f + __expf(-z0));
                    float f1 = 1.f / (1.f + __expf(-z1));
                    float2 kk2 = make_float2(1.f - f0, 1.f - f1);
                    float2 gg2 = make_float2(-log1pf(__expf(-f0)),
                                             -log1pf(__expf(-f1)));
                    *reinterpret_cast<float2*>(&C [(size_t)r * Nc + col]) = kk2;
                    *reinterpret_cast<float2*>(&C2[(size_t)r * Nc + col]) = gg2;
                } else {
                    float2 o = make_float2(z0, z1);
                    *reinterpret_cast<float2*>(&C[(size_t)r * Nc + col]) = o;
                }
            }
        }
    }
}

// ---------------------------------------------------------------------------
// GLA scan (from R3). Grid (32, 4, 4): x=(b,h), y=dv-block, z=dk-block.
// ---------------------------------------------------------------------------
__global__ __launch_bounds__(128)
void scan_kernel(const float* __restrict__ Q, const float* __restrict__ Kk,
                 const float* __restrict__ G, const float* __restrict__ V,
                 float* __restrict__ P0, float* __restrict__ P1,
                 float* __restrict__ P2, float* __restrict__ P3)
{
    __shared__ __align__(16) float qs[2][32];
    __shared__ __align__(16) float ksh[2][32];
    __shared__ __align__(16) float es[2][32];
    __shared__ __align__(16) float vs[2][32];

    const int bh  = blockIdx.x;
    const int dvb = blockIdx.y;
    const int dkb = blockIdx.z;
    const int b   = bh >> 3;
    const int h   = bh & 7;
    const int tid = threadIdx.x;
    const int dv_local = tid >> 2;
    const int dkq      = tid & 3;
    const int vcol     = dvb * 32 + dv_local;

    float* OP = (dkb == 0) ? P0 : (dkb == 1) ? P1 : (dkb == 2) ? P2 : P3;

    const size_t base = (size_t)b * NN * DD + (size_t)h * HDIM;

    float S[8];
    #pragma unroll
    for (int i = 0; i < 8; i++) S[i] = 0.f;

    size_t off = base;
    float r0 = 0.f, r1 = 0.f, r2 = 0.f;
    if (tid < 32) {
        r0 = Q [off + dkb*32 + tid];
        r1 = Kk[off + dkb*32 + tid];
        r2 = G [off + dkb*32 + tid];
    } else if (tid < 64) {
        r0 = V [off + dvb*32 + (tid - 32)];
    }

    #pragma unroll 1
    for (int tstep = 0; tstep < NN; tstep++) {
        const int bufi = tstep & 1;
        if (tid < 32) {
            qs [bufi][tid] = r0;
            ksh[bufi][tid] = r1;
            es [bufi][tid] = __expf(r2);
        } else if (tid < 64) {
            vs[bufi][tid - 32] = r0;
        }

        const size_t noff = off + DD;
        if (tstep + 1 < NN) {
            if (tid < 32) {
                r0 = Q [noff + dkb*32 + tid];
                r1 = Kk[noff + dkb*32 + tid];
                r2 = G [noff + dkb*32 + tid];
            } else if (tid < 64) {
                r0 = V [noff + dvb*32 + (tid - 32)];
            }
        }
        __syncthreads();

        const float4* q4 = reinterpret_cast<const float4*>(qs [bufi]);
        const float4* k4 = reinterpret_cast<const float4*>(ksh[bufi]);
        const float4* e4 = reinterpret_cast<const float4*>(es [bufi]);
        const float vv = vs[bufi][dv_local];

        float o = 0.f;
        #pragma unroll
        for (int j = 0; j < 2; j++) {
            const int fi = dkq * 2 + j;
            float4 qa = q4[fi], ka = k4[fi], ea = e4[fi];
            float s;
            s = fmaf(ea.x, S[4*j+0], ka.x * vv); S[4*j+0] = s; o = fmaf(qa.x, s, o);
            s = fmaf(ea.y, S[4*j+1], ka.y * vv); S[4*j+1] = s; o = fmaf(qa.y, s, o);
            s = fmaf(ea.z, S[4*j+2], ka.z * vv); S[4*j+2] = s; o = fmaf(qa.z, s, o);
            s = fmaf(ea.w, S[4*j+3], ka.w * vv); S[4*j+3] = s; o = fmaf(qa.w, s, o);
        }
        o += __shfl_xor_sync(0xffffffffu, o, 1);
        o += __shfl_xor_sync(0xffffffffu, o, 2);
        if (dkq == 0) OP[off + vcol] = o;

        off = noff;
    }
}

// ---------------------------------------------------------------------------
// Fused 4-way sum + RMSNorm over last dim (1024). Output pre-rounded to tf32
// (it feeds only the final tf32 GEMM; same numerics as rounding in-GEMM).
// ---------------------------------------------------------------------------
__global__ __launch_bounds__(256)
void rmsnorm_kernel(const float* __restrict__ X0, const float* __restrict__ X1,
                    const float* __restrict__ X2, const float* __restrict__ X3,
                    const float* __restrict__ w, float* __restrict__ Y)
{
    __shared__ float red[8];
    const int row = blockIdx.x;
    const int t = threadIdx.x;
    const size_t idx = (size_t)row * DD + t * 4;

    float4 a = *reinterpret_cast<const float4*>(&X0[idx]);
    float4 bq = *reinterpret_cast<const float4*>(&X1[idx]);
    float4 c = *reinterpret_cast<const float4*>(&X2[idx]);
    float4 d = *reinterpret_cast<const float4*>(&X3[idx]);
    float4 xv;
    xv.x = (a.x + bq.x) + (c.x + d.x);
    xv.y = (a.y + bq.y) + (c.y + d.y);
    xv.z = (a.z + bq.z) + (c.z + d.z);
    xv.w = (a.w + bq.w) + (c.w + d.w);

    float ss = xv.x*xv.x + xv.y*xv.y + xv.z*xv.z + xv.w*xv.w;
    #pragma unroll
    for (int o = 16; o; o >>= 1) ss += __shfl_xor_sync(0xffffffffu, ss, o);
    if ((t & 31) == 0) red[t >> 5] = ss;
    __syncthreads();
    if (t < 8) {
        float x = red[t];
        #pragma unroll
        for (int o = 4; o; o >>= 1) x += __shfl_xor_sync(0xffu, x, o);
        if (t == 0) red[0] = x;
    }
    __syncthreads();
    float inv = rsqrtf(red[0] * (1.f / DD) + 1e-6f);

    float4 wv = *reinterpret_cast<const float4*>(&w[t * 4]);
    float4 ov;
    ov.x = __uint_as_float(f2tf32(xv.x * inv * wv.x));
    ov.y = __uint_as_float(f2tf32(xv.y * inv * wv.y));
    ov.z = __uint_as_float(f2tf32(xv.z * inv * wv.z));
    ov.w = __uint_as_float(f2tf32(xv.w * inv * wv.w));
    *reinterpret_cast<float4*>(&Y[idx]) = ov;
}

// ---------------------------------------------------------------------------
extern "C" void kernel_launch(void* const* d_in, const int* in_sizes, int n_in,
                              void* d_out, int out_size)
{
    const float* x      = (const float*)d_in[0];
    const float* Wq     = (const float*)d_in[1];
    const float* Wk     = (const float*)d_in[2];
    const float* Wv     = (const float*)d_in[3];
    const float* Wo     = (const float*)d_in[4];
    const float* norm_w = (const float*)d_in[5];
    float* out = (float*)d_out;

    float *pq, *pk, *pg, *pv, *p0, *p1, *p2, *p3, *pnrm, *pcx, *pcw;
    cudaGetSymbolAddress((void**)&pq,   g_q);
    cudaGetSymbolAddress((void**)&pk,   g_k);
    cudaGetSymbolAddress((void**)&pg,   g_g);
    cudaGetSymbolAddress((void**)&pv,   g_v);
    cudaGetSymbolAddress((void**)&p0,   g_p0);
    cudaGetSymbolAddress((void**)&p1,   g_p1);
    cudaGetSymbolAddress((void**)&p2,   g_p2);
    cudaGetSymbolAddress((void**)&p3,   g_p3);
    cudaGetSymbolAddress((void**)&pnrm, g_nrm);
    cudaGetSymbolAddress((void**)&pcx,  g_cx);
    cudaGetSymbolAddress((void**)&pcw,  g_cw);
    float* pcw0 = pcw;
    float* pcw1 = pcw + (size_t)DD*DD;
    float* pcw2 = pcw + 2*(size_t)DD*DD;
    float* pcw3 = pcw + 3*(size_t)DD*DD;

    // Pre-pass: tf32-round x and weights
    const int n4x = MM * DD / 4;       // 2M
    const int n4w = DD * DD / 4;       // 256K
    cvt_tf32_kernel<<<(n4x + 255) / 256, 256>>>((const float4*)x,  (float4*)pcx,  n4x);
    cvt_tf32_kernel<<<(n4w + 255) / 256, 256>>>((const float4*)Wq, (float4*)pcw0, n4w);
    cvt_tf32_kernel<<<(n4w + 255) / 256, 256>>>((const float4*)Wk, (float4*)pcw1, n4w);
    cvt_tf32_kernel<<<(n4w + 255) / 256, 256>>>((const float4*)Wv, (float4*)pcw2, n4w);
    cvt_tf32_kernel<<<(n4w + 255) / 256, 256>>>((const float4*)Wo, (float4*)pcw3, n4w);

    dim3 gemm_grid(DD / 128, MM / 128);   // (8, 64)
    dim3 gemm_blk(256);

    // q = silu(x @ Wq^T)
    gemm_tc_kernel<0><<<gemm_grid, gemm_blk>>>(pcx, pcw0, pq, nullptr);
    // f = sigmoid(x @ Wk^T); k = 1-f; g = logsigmoid(f)
    gemm_tc_kernel<1><<<gemm_grid, gemm_blk>>>(pcx, pcw1, pk, pg);
    // v = x @ Wv^T
    gemm_tc_kernel<2><<<gemm_grid, gemm_blk>>>(pcx, pcw2, pv, nullptr);

    // GLA scan: 32 (b,h) x 4 dv-blocks x 4 dk-blocks = 512 blocks
    scan_kernel<<<dim3(BB * HH, 4, 4), 128>>>(pq, pk, pg, pv, p0, p1, p2, p3);

    // Fused partial-sum + RMSNorm (output tf32-rounded)
    rmsnorm_kernel<<<MM, 256>>>(p0, p1, p2, p3, norm_w, pnrm);

    // out = normed @ Wo^T
    gemm_tc_kernel<2><<<gemm_grid, gemm_blk>>>(pnrm, pcw3, out, nullptr);
}

// round 6
// speedup vs baseline: 2.8022x; 1.0827x over previous
#include <cuda_runtime.h>
#include <cuda_fp16.h>
#include <math.h>
#include <stdint.h>

// Problem constants
#define BB 4
#define NN 2048
#define DD 1024
#define HH 8
#define HDIM 128
#define MM (BB*NN)   // 8192 rows

// Scratch (allocation-free rule: __device__ globals)
__device__ float  g_q[(size_t)MM*DD];
__device__ float  g_k[(size_t)MM*DD];
__device__ float  g_g[(size_t)MM*DD];
__device__ float  g_v[(size_t)MM*DD];
__device__ float  g_p0[(size_t)MM*DD];
__device__ float  g_p1[(size_t)MM*DD];
__device__ float  g_p2[(size_t)MM*DD];
__device__ float  g_p3[(size_t)MM*DD];
__device__ __half g_hx[(size_t)MM*DD];      // x in fp16
__device__ __half g_hw[4*(size_t)DD*DD];    // weights in fp16
__device__ __half g_hnrm[(size_t)MM*DD];    // rmsnorm output in fp16

// ---------------------------------------------------------------------------
// helpers
// ---------------------------------------------------------------------------
__device__ __forceinline__ void mma_fp16(float c[4], const unsigned a[4],
                                         unsigned b0, unsigned b1) {
    asm volatile(
        "mma.sync.aligned.m16n8k16.row.col.f32.f16.f16.f32 "
        "{%0,%1,%2,%3},{%4,%5,%6,%7},{%8,%9},{%0,%1,%2,%3};"
        : "+f"(c[0]), "+f"(c[1]), "+f"(c[2]), "+f"(c[3])
        : "r"(a[0]), "r"(a[1]), "r"(a[2]), "r"(a[3]), "r"(b0), "r"(b1));
}

__device__ __forceinline__ void cp16(uint32_t dst, const void* src) {
    asm volatile("cp.async.cg.shared.global [%0], [%1], 16;"
                 :: "r"(dst), "l"(src));
}

__device__ __forceinline__ uint32_t s2u(const void* p) {
    uint32_t a;
    asm("{ .reg .u64 t; cvta.to.shared.u64 t, %1; cvt.u32.u64 %0, t; }"
        : "=r"(a) : "l"(p));
    return a;
}

// ---------------------------------------------------------------------------
// Pre-pass: fp32 -> fp16. Memory-bound.
// ---------------------------------------------------------------------------
__global__ __launch_bounds__(256)
void cvt_fp16_kernel(const float4* __restrict__ in, __half2* __restrict__ out,
                     int n4)
{
    int i = blockIdx.x * blockDim.x + threadIdx.x;
    if (i < n4) {
        float4 v = in[i];
        out[2*i]   = __floats2half2_rn(v.x, v.y);
        out[2*i+1] = __floats2half2_rn(v.z, v.w);
    }
}

// ---------------------------------------------------------------------------
// fp16 tensor-core GEMM: C[M,Nc] = epilogue( A[M,K] @ W[Nc,K]^T ).
// BM=BN=128, BK=32, 256 threads (8 warps 4x2), warp tile 32x64,
// mma.m16n8k16.f16 with fp32 accum. cp.async 2-stage double buffer.
// smem word = 2 halves; row stride 20 words (conflict-free frag loads,
// 16B-aligned rows for cp.async).
// MODE: 0 = SiLU, 1 = KG (k=1-f -> C, g=logsigmoid(f) -> C2), 2 = identity
// ---------------------------------------------------------------------------
template<int MODE>
__global__ __launch_bounds__(256, 2)
void gemm_fp16_kernel(const __half* __restrict__ A, const __half* __restrict__ W,
                      float* __restrict__ C, float* __restrict__ C2)
{
    const int K = DD, Nc = DD;
    __shared__ unsigned As[2][128][20];
    __shared__ unsigned Bs[2][128][20];

    const int bm = blockIdx.y * 128;
    const int bn = blockIdx.x * 128;
    const int t  = threadIdx.x;
    const int warp = t >> 5, lane = t & 31;
    const int wm = (warp >> 1) * 32;
    const int wn = (warp & 1) * 64;
    const int qrow = lane >> 2;        // 0..7
    const int qcol = lane & 3;         // 0..3

    float acc[2][8][4];
    #pragma unroll
    for (int mt = 0; mt < 2; mt++)
        #pragma unroll
        for (int nt = 0; nt < 8; nt++)
            #pragma unroll
            for (int i = 0; i < 4; i++) acc[mt][nt][i] = 0.f;

    // per-thread cp.async pattern: 2 segments each for A and B
    // idx in 0..511: row = idx>>2 (0..127), seg = idx&3 (16B = 4 words = 8 halves)
    int rowv[2], segv[2];
    #pragma unroll
    for (int r = 0; r < 2; r++) {
        int idx = t + r * 256;
        rowv[r] = idx >> 2;
        segv[r] = idx & 3;
    }

    // prefetch chunk 0
    #pragma unroll
    for (int r = 0; r < 2; r++) {
        cp16(s2u(&As[0][rowv[r]][segv[r]*4]),
             &A[(size_t)(bm + rowv[r]) * K + segv[r]*8]);
        cp16(s2u(&Bs[0][rowv[r]][segv[r]*4]),
             &W[(size_t)(bn + rowv[r]) * K + segv[r]*8]);
    }
    asm volatile("cp.async.commit_group;" ::: "memory");

    const int NCH = K / 32;   // 32 chunks (32 halves = 16 words each)
    #pragma unroll 1
    for (int ch = 0; ch < NCH; ch++) {
        const int buf = ch & 1;
        if (ch + 1 < NCH) {
            const int k0n = (ch + 1) * 32;
            #pragma unroll
            for (int r = 0; r < 2; r++) {
                cp16(s2u(&As[buf ^ 1][rowv[r]][segv[r]*4]),
                     &A[(size_t)(bm + rowv[r]) * K + k0n + segv[r]*8]);
                cp16(s2u(&Bs[buf ^ 1][rowv[r]][segv[r]*4]),
                     &W[(size_t)(bn + rowv[r]) * K + k0n + segv[r]*8]);
            }
            asm volatile("cp.async.commit_group;" ::: "memory");
            asm volatile("cp.async.wait_group 1;" ::: "memory");
        } else {
            asm volatile("cp.async.wait_group 0;" ::: "memory");
        }
        __syncthreads();

        // two k16 MMA steps per 32-half chunk
        #pragma unroll
        for (int ks = 0; ks < 2; ks++) {
            const int kk = ks * 8;
            unsigned a[2][4];
            #pragma unroll
            for (int mt = 0; mt < 2; mt++) {
                int r0 = wm + mt * 16 + qrow;
                a[mt][0] = As[buf][r0    ][kk + qcol];
                a[mt][1] = As[buf][r0 + 8][kk + qcol];
                a[mt][2] = As[buf][r0    ][kk + qcol + 4];
                a[mt][3] = As[buf][r0 + 8][kk + qcol + 4];
            }
            #pragma unroll
            for (int nt = 0; nt < 8; nt++) {
                int c0 = wn + nt * 8 + qrow;
                unsigned b0 = Bs[buf][c0][kk + qcol];
                unsigned b1 = Bs[buf][c0][kk + qcol + 4];
                mma_fp16(acc[0][nt], a[0], b0, b1);
                mma_fp16(acc[1][nt], a[1], b0, b1);
            }
        }
        __syncthreads();
    }

    // Epilogue
    #pragma unroll
    for (int mt = 0; mt < 2; mt++) {
        #pragma unroll
        for (int nt = 0; nt < 8; nt++) {
            int row = bm + wm + mt * 16 + qrow;
            int col = bn + wn + nt * 8 + qcol * 2;
            #pragma unroll
            for (int half = 0; half < 2; half++) {
                int r = row + half * 8;
                float z0 = acc[mt][nt][half * 2 + 0];
                float z1 = acc[mt][nt][half * 2 + 1];
                if (MODE == 0) {
                    float s0 = 1.f / (1.f + __expf(-z0));
                    float s1 = 1.f / (1.f + __expf(-z1));
                    float2 o = make_float2(z0 * s0, z1 * s1);
                    *reinterpret_cast<float2*>(&C[(size_t)r * Nc + col]) = o;
                } else if (MODE == 1) {
                    float f0 = 1.f / (1.f + __expf(-z0));
                    float f1 = 1.f / (1.f + __expf(-z1));
                    float2 kk2 = make_float2(1.f - f0, 1.f - f1);
                    float2 gg2 = make_float2(-log1pf(__expf(-f0)),
                                             -log1pf(__expf(-f1)));
                    *reinterpret_cast<float2*>(&C [(size_t)r * Nc + col]) = kk2;
                    *reinterpret_cast<float2*>(&C2[(size_t)r * Nc + col]) = gg2;
                } else {
                    float2 o = make_float2(z0, z1);
                    *reinterpret_cast<float2*>(&C[(size_t)r * Nc + col]) = o;
                }
            }
        }
    }
}

// ---------------------------------------------------------------------------
// GLA scan v4: per-warp staging, NO block barrier. Grid (32,4,4):
// x=(b,h), y=dv-block(32), z=dk-block(32). 128 threads = 4 independent warps;
// each warp stages the full 32-wide dk-block into its own smem slice and
// syncs with __syncwarp only. Thread = (dv_local=tid>>2, dkq=tid&3) owns
// 8 S values; partial o reduced over the 4 dkq lanes by shfl.
// ---------------------------------------------------------------------------
__global__ __launch_bounds__(128)
void scan_kernel(const float* __restrict__ Q, const float* __restrict__ Kk,
                 const float* __restrict__ G, const float* __restrict__ V,
                 float* __restrict__ P0, float* __restrict__ P1,
                 float* __restrict__ P2, float* __restrict__ P3)
{
    __shared__ __align__(16) float qs [2][4][32];
    __shared__ __align__(16) float ksh[2][4][32];
    __shared__ __align__(16) float es [2][4][32];

    const int bh  = blockIdx.x;
    const int dvb = blockIdx.y;
    const int dkb = blockIdx.z;
    const int b   = bh >> 3;
    const int h   = bh & 7;
    const int tid = threadIdx.x;
    const int wid = tid >> 5, lane = tid & 31;
    const int dv_local = tid >> 2;
    const int dkq      = tid & 3;
    const int vcol     = dvb * 32 + dv_local;

    float* OP = (dkb == 0) ? P0 : (dkb == 1) ? P1 : (dkb == 2) ? P2 : P3;

    const size_t base = (size_t)b * NN * DD + (size_t)h * HDIM;

    float S[8];
    #pragma unroll
    for (int i = 0; i < 8; i++) S[i] = 0.f;

    // lane stages dk_local = lane (per warp); v loaded per-thread (quad bcast)
    size_t off = base;
    float r0 = Q [off + dkb*32 + lane];
    float r1 = Kk[off + dkb*32 + lane];
    float r2 = G [off + dkb*32 + lane];
    float rv = V [off + vcol];

    #pragma unroll 1
    for (int tstep = 0; tstep < NN; tstep++) {
        const int bufi = tstep & 1;
        qs [bufi][wid][lane] = r0;
        ksh[bufi][wid][lane] = r1;
        es [bufi][wid][lane] = __expf(r2);
        const float vv = rv;

        const size_t noff = off + DD;
        if (tstep + 1 < NN) {
            r0 = Q [noff + dkb*32 + lane];
            r1 = Kk[noff + dkb*32 + lane];
            r2 = G [noff + dkb*32 + lane];
            rv = V [noff + vcol];
        }
        __syncwarp();

        const float4* q4 = reinterpret_cast<const float4*>(qs [bufi][wid]);
        const float4* k4 = reinterpret_cast<const float4*>(ksh[bufi][wid]);
        const float4* e4 = reinterpret_cast<const float4*>(es [bufi][wid]);

        float o = 0.f;
        #pragma unroll
        for (int j = 0; j < 2; j++) {
            const int fi = dkq * 2 + j;
            float4 qa = q4[fi], ka = k4[fi], ea = e4[fi];
            float s;
            s = fmaf(ea.x, S[4*j+0], ka.x * vv); S[4*j+0] = s; o = fmaf(qa.x, s, o);
            s = fmaf(ea.y, S[4*j+1], ka.y * vv); S[4*j+1] = s; o = fmaf(qa.y, s, o);
            s = fmaf(ea.z, S[4*j+2], ka.z * vv); S[4*j+2] = s; o = fmaf(qa.z, s, o);
            s = fmaf(ea.w, S[4*j+3], ka.w * vv); S[4*j+3] = s; o = fmaf(qa.w, s, o);
        }
        o += __shfl_xor_sync(0xffffffffu, o, 1);
        o += __shfl_xor_sync(0xffffffffu, o, 2);
        if (dkq == 0) OP[off + vcol] = o;

        off = noff;
    }
}

// ---------------------------------------------------------------------------
// Fused 4-way sum + RMSNorm over last dim (1024). Emits fp16 for final GEMM.
// ---------------------------------------------------------------------------
__global__ __launch_bounds__(256)
void rmsnorm_kernel(const float* __restrict__ X0, const float* __restrict__ X1,
                    const float* __restrict__ X2, const float* __restrict__ X3,
                    const float* __restrict__ w, __half2* __restrict__ Y)
{
    __shared__ float red[8];
    const int row = blockIdx.x;
    const int t = threadIdx.x;
    const size_t idx = (size_t)row * DD + t * 4;

    float4 a = *reinterpret_cast<const float4*>(&X0[idx]);
    float4 bq = *reinterpret_cast<const float4*>(&X1[idx]);
    float4 c = *reinterpret_cast<const float4*>(&X2[idx]);
    float4 d = *reinterpret_cast<const float4*>(&X3[idx]);
    float4 xv;
    xv.x = (a.x + bq.x) + (c.x + d.x);
    xv.y = (a.y + bq.y) + (c.y + d.y);
    xv.z = (a.z + bq.z) + (c.z + d.z);
    xv.w = (a.w + bq.w) + (c.w + d.w);

    float ss = xv.x*xv.x + xv.y*xv.y + xv.z*xv.z + xv.w*xv.w;
    #pragma unroll
    for (int o = 16; o; o >>= 1) ss += __shfl_xor_sync(0xffffffffu, ss, o);
    if ((t & 31) == 0) red[t >> 5] = ss;
    __syncthreads();
    if (t < 8) {
        float x = red[t];
        #pragma unroll
        for (int o = 4; o; o >>= 1) x += __shfl_xor_sync(0xffu, x, o);
        if (t == 0) red[0] = x;
    }
    __syncthreads();
    float inv = rsqrtf(red[0] * (1.f / DD) + 1e-6f);

    float4 wv = *reinterpret_cast<const float4*>(&w[t * 4]);
    size_t o2 = (size_t)row * (DD/2) + t * 2;
    Y[o2]   = __floats2half2_rn(xv.x * inv * wv.x, xv.y * inv * wv.y);
    Y[o2+1] = __floats2half2_rn(xv.z * inv * wv.z, xv.w * inv * wv.w);
}

// ---------------------------------------------------------------------------
extern "C" void kernel_launch(void* const* d_in, const int* in_sizes, int n_in,
                              void* d_out, int out_size)
{
    const float* x      = (const float*)d_in[0];
    const float* Wq     = (const float*)d_in[1];
    const float* Wk     = (const float*)d_in[2];
    const float* Wv     = (const float*)d_in[3];
    const float* Wo     = (const float*)d_in[4];
    const float* norm_w = (const float*)d_in[5];
    float* out = (float*)d_out;

    float *pq, *pk, *pg, *pv, *p0, *p1, *p2, *p3;
    __half *phx, *phw, *phnrm;
    cudaGetSymbolAddress((void**)&pq,    g_q);
    cudaGetSymbolAddress((void**)&pk,    g_k);
    cudaGetSymbolAddress((void**)&pg,    g_g);
    cudaGetSymbolAddress((void**)&pv,    g_v);
    cudaGetSymbolAddress((void**)&p0,    g_p0);
    cudaGetSymbolAddress((void**)&p1,    g_p1);
    cudaGetSymbolAddress((void**)&p2,    g_p2);
    cudaGetSymbolAddress((void**)&p3,    g_p3);
    cudaGetSymbolAddress((void**)&phx,   g_hx);
    cudaGetSymbolAddress((void**)&phw,   g_hw);
    cudaGetSymbolAddress((void**)&phnrm, g_hnrm);
    __half* phw0 = phw;
    __half* phw1 = phw + (size_t)DD*DD;
    __half* phw2 = phw + 2*(size_t)DD*DD;
    __half* phw3 = phw + 3*(size_t)DD*DD;

    // Pre-pass: fp32 -> fp16 for x and weights
    const int n4x = MM * DD / 4;
    const int n4w = DD * DD / 4;
    cvt_fp16_kernel<<<(n4x + 255) / 256, 256>>>((const float4*)x,  (__half2*)phx,  n4x);
    cvt_fp16_kernel<<<(n4w + 255) / 256, 256>>>((const float4*)Wq, (__half2*)phw0, n4w);
    cvt_fp16_kernel<<<(n4w + 255) / 256, 256>>>((const float4*)Wk, (__half2*)phw1, n4w);
    cvt_fp16_kernel<<<(n4w + 255) / 256, 256>>>((const float4*)Wv, (__half2*)phw2, n4w);
    cvt_fp16_kernel<<<(n4w + 255) / 256, 256>>>((const float4*)Wo, (__half2*)phw3, n4w);

    dim3 gemm_grid(DD / 128, MM / 128);   // (8, 64)
    dim3 gemm_blk(256);

    // q = silu(x @ Wq^T)
    gemm_fp16_kernel<0><<<gemm_grid, gemm_blk>>>(phx, phw0, pq, nullptr);
    // f = sigmoid(x @ Wk^T); k = 1-f; g = logsigmoid(f)
    gemm_fp16_kernel<1><<<gemm_grid, gemm_blk>>>(phx, phw1, pk, pg);
    // v = x @ Wv^T
    gemm_fp16_kernel<2><<<gemm_grid, gemm_blk>>>(phx, phw2, pv, nullptr);

    // GLA scan: 32 (b,h) x 4 dv-blocks x 4 dk-blocks = 512 blocks
    scan_kernel<<<dim3(BB * HH, 4, 4), 128>>>(pq, pk, pg, pv, p0, p1, p2, p3);

    // Fused partial-sum + RMSNorm (fp16 output)
    rmsnorm_kernel<<<MM, 256>>>(p0, p1, p2, p3, norm_w, (__half2*)phnrm);

    // out = normed @ Wo^T
    gemm_fp16_kernel<2><<<gemm_grid, gemm_blk>>>(phnrm, phw3, out, nullptr);
}

// round 7
// speedup vs baseline: 2.9396x; 1.0490x over previous
#include <cuda_runtime.h>
#include <cuda_fp16.h>
#include <math.h>
#include <stdint.h>

// Problem constants
#define BB 4
#define NN 2048
#define DD 1024
#define HH 8
#define HDIM 128
#define MM (BB*NN)   // 8192 rows

// Scratch (allocation-free rule: __device__ globals)
__device__ float  g_q[(size_t)MM*DD];
__device__ float  g_k[(size_t)MM*DD];
__device__ float  g_g[(size_t)MM*DD];
__device__ float  g_v[(size_t)MM*DD];
__device__ float  g_p0[(size_t)MM*DD];
__device__ float  g_p1[(size_t)MM*DD];
__device__ float  g_p2[(size_t)MM*DD];
__device__ float  g_p3[(size_t)MM*DD];
__device__ __half g_hx[(size_t)MM*DD];      // x in fp16
__device__ __half g_hw[4*(size_t)DD*DD];    // weights in fp16
__device__ __half g_hnrm[(size_t)MM*DD];    // rmsnorm output in fp16

// ---------------------------------------------------------------------------
// helpers
// ---------------------------------------------------------------------------
__device__ __forceinline__ void mma_fp16(float c[4], const uint32_t a[4],
                                         uint32_t b0, uint32_t b1) {
    asm volatile(
        "mma.sync.aligned.m16n8k16.row.col.f32.f16.f16.f32 "
        "{%0,%1,%2,%3},{%4,%5,%6,%7},{%8,%9},{%0,%1,%2,%3};"
        : "+f"(c[0]), "+f"(c[1]), "+f"(c[2]), "+f"(c[3])
        : "r"(a[0]), "r"(a[1]), "r"(a[2]), "r"(a[3]), "r"(b0), "r"(b1));
}

__device__ __forceinline__ void ldm_x4(uint32_t r[4], uint32_t addr) {
    asm volatile(
        "ldmatrix.sync.aligned.m8n8.x4.shared.b16 {%0,%1,%2,%3}, [%4];"
        : "=r"(r[0]), "=r"(r[1]), "=r"(r[2]), "=r"(r[3]) : "r"(addr));
}

__device__ __forceinline__ void cp16(uint32_t dst, const void* src) {
    asm volatile("cp.async.cg.shared.global [%0], [%1], 16;"
                 :: "r"(dst), "l"(src));
}

__device__ __forceinline__ uint32_t s2u(const void* p) {
    uint32_t a;
    asm("{ .reg .u64 t; cvta.to.shared.u64 t, %1; cvt.u32.u64 %0, t; }"
        : "=r"(a) : "l"(p));
    return a;
}

// ---------------------------------------------------------------------------
// Pre-pass: fp32 -> fp16. Memory-bound.
// ---------------------------------------------------------------------------
__global__ __launch_bounds__(256)
void cvt_fp16_kernel(const float4* __restrict__ in, __half2* __restrict__ out,
                     int n4)
{
    int i = blockIdx.x * blockDim.x + threadIdx.x;
    if (i < n4) {
        float4 v = in[i];
        out[2*i]   = __floats2half2_rn(v.x, v.y);
        out[2*i+1] = __floats2half2_rn(v.z, v.w);
    }
}

// ---------------------------------------------------------------------------
// fp16 tensor-core GEMM v2: C[M,Nc] = epilogue( A[M,K] @ W[Nc,K]^T ).
// BM=BN=128, BK=64 halves, 256 threads (8 warps 4x2), warp tile 32x64.
// ldmatrix.x4 frag loads, cp.async 2-stage double buffer, 2 barriers/chunk.
// smem rows: 72 halves stride (144B: 16B-aligned, ldmatrix conflict-free).
// MODE: 0 = SiLU, 1 = KG (k=1-f -> C, g=logsigmoid(f) -> C2), 2 = identity
// ---------------------------------------------------------------------------
#define RS 72                                  // row stride (halves)
#define ABUF_BYTES (128 * RS * 2)              // 18432 B per operand per buf
#define BREG_BYTES (2 * ABUF_BYTES)            // B region base = 36864
#define GEMM_SMEM_BYTES (4 * ABUF_BYTES)       // 73728 B

template<int MODE>
__global__ __launch_bounds__(256, 2)
void gemm_fp16_kernel(const __half* __restrict__ A, const __half* __restrict__ W,
                      float* __restrict__ C, float* __restrict__ C2)
{
    const int K = DD, Nc = DD;
    extern __shared__ __align__(16) __half smem_raw[];
    const uint32_t sb = s2u(smem_raw);

    const int bm = blockIdx.y * 128;
    const int bn = blockIdx.x * 128;
    const int t  = threadIdx.x;
    const int warp = t >> 5, lane = t & 31;
    const int wm = (warp >> 1) * 32;
    const int wn = (warp & 1) * 64;
    const int qrow = lane >> 2;        // 0..7
    const int qcol = lane & 3;         // 0..3

    float acc[2][8][4];
    #pragma unroll
    for (int mt = 0; mt < 2; mt++)
        #pragma unroll
        for (int nt = 0; nt < 8; nt++)
            #pragma unroll
            for (int i = 0; i < 4; i++) acc[mt][nt][i] = 0.f;

    // cp.async pattern: 1024 16B-segments per operand per chunk, 4 per thread
    int rowv[4], segv[4];
    #pragma unroll
    for (int r = 0; r < 4; r++) {
        int idx = t + r * 256;       // 0..1023
        rowv[r] = idx >> 3;          // 0..127
        segv[r] = idx & 7;           // 0..7 (8 halves each)
    }

    // ldmatrix per-lane byte offsets (within a buffer)
    const int lgrp = lane >> 3, lrow = lane & 7;
    uint32_t aoffb[2], boffb[4];
    #pragma unroll
    for (int mt = 0; mt < 2; mt++) {
        int row = wm + mt * 16 + (lgrp & 1) * 8 + lrow;
        aoffb[mt] = (uint32_t)(row * RS + (lgrp >> 1) * 8) * 2;
    }
    #pragma unroll
    for (int p = 0; p < 4; p++) {
        int row = wn + p * 16 + (lgrp >> 1) * 8 + lrow;
        boffb[p] = (uint32_t)(row * RS + (lgrp & 1) * 8) * 2 + BREG_BYTES;
    }

    // prefetch chunk 0
    #pragma unroll
    for (int r = 0; r < 4; r++) {
        uint32_t so = (uint32_t)(rowv[r] * RS + segv[r] * 8) * 2;
        cp16(sb + so,             &A[(size_t)(bm + rowv[r]) * K + segv[r] * 8]);
        cp16(sb + BREG_BYTES + so, &W[(size_t)(bn + rowv[r]) * K + segv[r] * 8]);
    }
    asm volatile("cp.async.commit_group;" ::: "memory");

    const int NCH = K / 64;   // 16 chunks
    #pragma unroll 1
    for (int ch = 0; ch < NCH; ch++) {
        const uint32_t bufB = (uint32_t)(ch & 1) * ABUF_BYTES;
        if (ch + 1 < NCH) {
            const uint32_t nbufB = (uint32_t)((ch + 1) & 1) * ABUF_BYTES;
            const int k0n = (ch + 1) * 64;
            #pragma unroll
            for (int r = 0; r < 4; r++) {
                uint32_t so = (uint32_t)(rowv[r] * RS + segv[r] * 8) * 2;
                cp16(sb + nbufB + so,
                     &A[(size_t)(bm + rowv[r]) * K + k0n + segv[r] * 8]);
                cp16(sb + BREG_BYTES + nbufB + so,
                     &W[(size_t)(bn + rowv[r]) * K + k0n + segv[r] * 8]);
            }
            asm volatile("cp.async.commit_group;" ::: "memory");
            asm volatile("cp.async.wait_group 1;" ::: "memory");
        } else {
            asm volatile("cp.async.wait_group 0;" ::: "memory");
        }
        __syncthreads();

        // 4 k16 steps
        #pragma unroll
        for (int ks = 0; ks < 4; ks++) {
            const uint32_t kb = sb + bufB + (uint32_t)ks * 32;   // 16 halves
            uint32_t a0[4], a1[4];
            ldm_x4(a0, kb + aoffb[0]);
            ldm_x4(a1, kb + aoffb[1]);
            #pragma unroll
            for (int p = 0; p < 4; p++) {
                uint32_t bb[4];
                ldm_x4(bb, kb + boffb[p]);
                mma_fp16(acc[0][2*p],   a0, bb[0], bb[1]);
                mma_fp16(acc[1][2*p],   a1, bb[0], bb[1]);
                mma_fp16(acc[0][2*p+1], a0, bb[2], bb[3]);
                mma_fp16(acc[1][2*p+1], a1, bb[2], bb[3]);
            }
        }
        __syncthreads();   // all reads of bufB done before it is refilled
    }

    // Epilogue
    #pragma unroll
    for (int mt = 0; mt < 2; mt++) {
        #pragma unroll
        for (int nt = 0; nt < 8; nt++) {
            int row = bm + wm + mt * 16 + qrow;
            int col = bn + wn + nt * 8 + qcol * 2;
            #pragma unroll
            for (int half = 0; half < 2; half++) {
                int r = row + half * 8;
                float z0 = acc[mt][nt][half * 2 + 0];
                float z1 = acc[mt][nt][half * 2 + 1];
                if (MODE == 0) {
                    float s0 = 1.f / (1.f + __expf(-z0));
                    float s1 = 1.f / (1.f + __expf(-z1));
                    float2 o = make_float2(z0 * s0, z1 * s1);
                    *reinterpret_cast<float2*>(&C[(size_t)r * Nc + col]) = o;
                } else if (MODE == 1) {
                    float f0 = 1.f / (1.f + __expf(-z0));
                    float f1 = 1.f / (1.f + __expf(-z1));
                    float2 kk2 = make_float2(1.f - f0, 1.f - f1);
                    float2 gg2 = make_float2(-log1pf(__expf(-f0)),
                                             -log1pf(__expf(-f1)));
                    *reinterpret_cast<float2*>(&C [(size_t)r * Nc + col]) = kk2;
                    *reinterpret_cast<float2*>(&C2[(size_t)r * Nc + col]) = gg2;
                } else {
                    float2 o = make_float2(z0, z1);
                    *reinterpret_cast<float2*>(&C[(size_t)r * Nc + col]) = o;
                }
            }
        }
    }
}

// ---------------------------------------------------------------------------
// GLA scan v4: per-warp staging, warp-level sync only. Grid (32,4,4).
// ---------------------------------------------------------------------------
__global__ __launch_bounds__(128)
void scan_kernel(const float* __restrict__ Q, const float* __restrict__ Kk,
                 const float* __restrict__ G, const float* __restrict__ V,
                 float* __restrict__ P0, float* __restrict__ P1,
                 float* __restrict__ P2, float* __restrict__ P3)
{
    __shared__ __align__(16) float qs [2][4][32];
    __shared__ __align__(16) float ksh[2][4][32];
    __shared__ __align__(16) float es [2][4][32];

    const int bh  = blockIdx.x;
    const int dvb = blockIdx.y;
    const int dkb = blockIdx.z;
    const int b   = bh >> 3;
    const int h   = bh & 7;
    const int tid = threadIdx.x;
    const int wid = tid >> 5, lane = tid & 31;
    const int dv_local = tid >> 2;
    const int dkq      = tid & 3;
    const int vcol     = dvb * 32 + dv_local;

    float* OP = (dkb == 0) ? P0 : (dkb == 1) ? P1 : (dkb == 2) ? P2 : P3;

    const size_t base = (size_t)b * NN * DD + (size_t)h * HDIM;

    float S[8];
    #pragma unroll
    for (int i = 0; i < 8; i++) S[i] = 0.f;

    size_t off = base;
    float r0 = Q [off + dkb*32 + lane];
    float r1 = Kk[off + dkb*32 + lane];
    float r2 = G [off + dkb*32 + lane];
    float rv = V [off + vcol];

    #pragma unroll 1
    for (int tstep = 0; tstep < NN; tstep++) {
        const int bufi = tstep & 1;
        qs [bufi][wid][lane] = r0;
        ksh[bufi][wid][lane] = r1;
        es [bufi][wid][lane] = __expf(r2);
        const float vv = rv;

        const size_t noff = off + DD;
        if (tstep + 1 < NN) {
            r0 = Q [noff + dkb*32 + lane];
            r1 = Kk[noff + dkb*32 + lane];
            r2 = G [noff + dkb*32 + lane];
            rv = V [noff + vcol];
        }
        __syncwarp();

        const float4* q4 = reinterpret_cast<const float4*>(qs [bufi][wid]);
        const float4* k4 = reinterpret_cast<const float4*>(ksh[bufi][wid]);
        const float4* e4 = reinterpret_cast<const float4*>(es [bufi][wid]);

        float o = 0.f;
        #pragma unroll
        for (int j = 0; j < 2; j++) {
            const int fi = dkq * 2 + j;
            float4 qa = q4[fi], ka = k4[fi], ea = e4[fi];
            float s;
            s = fmaf(ea.x, S[4*j+0], ka.x * vv); S[4*j+0] = s; o = fmaf(qa.x, s, o);
            s = fmaf(ea.y, S[4*j+1], ka.y * vv); S[4*j+1] = s; o = fmaf(qa.y, s, o);
            s = fmaf(ea.z, S[4*j+2], ka.z * vv); S[4*j+2] = s; o = fmaf(qa.z, s, o);
            s = fmaf(ea.w, S[4*j+3], ka.w * vv); S[4*j+3] = s; o = fmaf(qa.w, s, o);
        }
        o += __shfl_xor_sync(0xffffffffu, o, 1);
        o += __shfl_xor_sync(0xffffffffu, o, 2);
        if (dkq == 0) OP[off + vcol] = o;

        off = noff;
    }
}

// ---------------------------------------------------------------------------
// Fused 4-way sum + RMSNorm over last dim (1024). Emits fp16 for final GEMM.
// ---------------------------------------------------------------------------
__global__ __launch_bounds__(256)
void rmsnorm_kernel(const float* __restrict__ X0, const float* __restrict__ X1,
                    const float* __restrict__ X2, const float* __restrict__ X3,
                    const float* __restrict__ w, __half2* __restrict__ Y)
{
    __shared__ float red[8];
    const int row = blockIdx.x;
    const int t = threadIdx.x;
    const size_t idx = (size_t)row * DD + t * 4;

    float4 a = *reinterpret_cast<const float4*>(&X0[idx]);
    float4 bq = *reinterpret_cast<const float4*>(&X1[idx]);
    float4 c = *reinterpret_cast<const float4*>(&X2[idx]);
    float4 d = *reinterpret_cast<const float4*>(&X3[idx]);
    float4 xv;
    xv.x = (a.x + bq.x) + (c.x + d.x);
    xv.y = (a.y + bq.y) + (c.y + d.y);
    xv.z = (a.z + bq.z) + (c.z + d.z);
    xv.w = (a.w + bq.w) + (c.w + d.w);

    float ss = xv.x*xv.x + xv.y*xv.y + xv.z*xv.z + xv.w*xv.w;
    #pragma unroll
    for (int o = 16; o; o >>= 1) ss += __shfl_xor_sync(0xffffffffu, ss, o);
    if ((t & 31) == 0) red[t >> 5] = ss;
    __syncthreads();
    if (t < 8) {
        float x = red[t];
        #pragma unroll
        for (int o = 4; o; o >>= 1) x += __shfl_xor_sync(0xffu, x, o);
        if (t == 0) red[0] = x;
    }
    __syncthreads();
    float inv = rsqrtf(red[0] * (1.f / DD) + 1e-6f);

    float4 wv = *reinterpret_cast<const float4*>(&w[t * 4]);
    size_t o2 = (size_t)row * (DD/2) + t * 2;
    Y[o2]   = __floats2half2_rn(xv.x * inv * wv.x, xv.y * inv * wv.y);
    Y[o2+1] = __floats2half2_rn(xv.z * inv * wv.z, xv.w * inv * wv.w);
}

// ---------------------------------------------------------------------------
extern "C" void kernel_launch(void* const* d_in, const int* in_sizes, int n_in,
                              void* d_out, int out_size)
{
    const float* x      = (const float*)d_in[0];
    const float* Wq     = (const float*)d_in[1];
    const float* Wk     = (const float*)d_in[2];
    const float* Wv     = (const float*)d_in[3];
    const float* Wo     = (const float*)d_in[4];
    const float* norm_w = (const float*)d_in[5];
    float* out = (float*)d_out;

    float *pq, *pk, *pg, *pv, *p0, *p1, *p2, *p3;
    __half *phx, *phw, *phnrm;
    cudaGetSymbolAddress((void**)&pq,    g_q);
    cudaGetSymbolAddress((void**)&pk,    g_k);
    cudaGetSymbolAddress((void**)&pg,    g_g);
    cudaGetSymbolAddress((void**)&pv,    g_v);
    cudaGetSymbolAddress((void**)&p0,    g_p0);
    cudaGetSymbolAddress((void**)&p1,    g_p1);
    cudaGetSymbolAddress((void**)&p2,    g_p2);
    cudaGetSymbolAddress((void**)&p3,    g_p3);
    cudaGetSymbolAddress((void**)&phx,   g_hx);
    cudaGetSymbolAddress((void**)&phw,   g_hw);
    cudaGetSymbolAddress((void**)&phnrm, g_hnrm);
    __half* phw0 = phw;
    __half* phw1 = phw + (size_t)DD*DD;
    __half* phw2 = phw + 2*(size_t)DD*DD;
    __half* phw3 = phw + 3*(size_t)DD*DD;

    // Pre-pass: fp32 -> fp16 for x and weights
    const int n4x = MM * DD / 4;
    const int n4w = DD * DD / 4;
    cvt_fp16_kernel<<<(n4x + 255) / 256, 256>>>((const float4*)x,  (__half2*)phx,  n4x);
    cvt_fp16_kernel<<<(n4w + 255) / 256, 256>>>((const float4*)Wq, (__half2*)phw0, n4w);
    cvt_fp16_kernel<<<(n4w + 255) / 256, 256>>>((const float4*)Wk, (__half2*)phw1, n4w);
    cvt_fp16_kernel<<<(n4w + 255) / 256, 256>>>((const float4*)Wv, (__half2*)phw2, n4w);
    cvt_fp16_kernel<<<(n4w + 255) / 256, 256>>>((const float4*)Wo, (__half2*)phw3, n4w);

    cudaFuncSetAttribute(gemm_fp16_kernel<0>,
        cudaFuncAttributeMaxDynamicSharedMemorySize, GEMM_SMEM_BYTES);
    cudaFuncSetAttribute(gemm_fp16_kernel<1>,
        cudaFuncAttributeMaxDynamicSharedMemorySize, GEMM_SMEM_BYTES);
    cudaFuncSetAttribute(gemm_fp16_kernel<2>,
        cudaFuncAttributeMaxDynamicSharedMemorySize, GEMM_SMEM_BYTES);

    dim3 gemm_grid(DD / 128, MM / 128);   // (8, 64)
    dim3 gemm_blk(256);

    // q = silu(x @ Wq^T)
    gemm_fp16_kernel<0><<<gemm_grid, gemm_blk, GEMM_SMEM_BYTES>>>(phx, phw0, pq, nullptr);
    // f = sigmoid(x @ Wk^T); k = 1-f; g = logsigmoid(f)
    gemm_fp16_kernel<1><<<gemm_grid, gemm_blk, GEMM_SMEM_BYTES>>>(phx, phw1, pk, pg);
    // v = x @ Wv^T
    gemm_fp16_kernel<2><<<gemm_grid, gemm_blk, GEMM_SMEM_BYTES>>>(phx, phw2, pv, nullptr);

    // GLA scan: 32 (b,h) x 4 dv-blocks x 4 dk-blocks = 512 blocks
    scan_kernel<<<dim3(BB * HH, 4, 4), 128>>>(pq, pk, pg, pv, p0, p1, p2, p3);

    // Fused partial-sum + RMSNorm (fp16 output)
    rmsnorm_kernel<<<MM, 256>>>(p0, p1, p2, p3, norm_w, (__half2*)phnrm);

    // out = normed @ Wo^T
    gemm_fp16_kernel<2><<<gemm_grid, gemm_blk, GEMM_SMEM_BYTES>>>(phnrm, phw3, out, nullptr);
}

// round 9
// speedup vs baseline: 3.6168x; 1.2304x over previous
#include <cuda_runtime.h>
#include <cuda_fp16.h>
#include <math.h>
#include <stdint.h>

// Problem constants
#define BB 4
#define NN 2048
#define DD 1024
#define HH 8
#define HDIM 128
#define MM (BB*NN)     // 8192 rows
#define TCH 512        // sequence chunk length
#define RCH 2048       // rows per chunk (BB*TCH)

// Scratch (allocation-free rule: __device__ globals)
__device__ float  g_q[(size_t)MM*DD];
__device__ float  g_k[(size_t)MM*DD];
__device__ float  g_g[(size_t)MM*DD];
__device__ float  g_v[(size_t)MM*DD];
__device__ float  g_p0[(size_t)MM*DD];
__device__ float  g_p1[(size_t)MM*DD];
__device__ float  g_p2[(size_t)MM*DD];
__device__ float  g_p3[(size_t)MM*DD];
__device__ float  g_state[512*128*8];        // scan state between chunks
__device__ __half g_hx[(size_t)MM*DD];       // x in fp16
__device__ __half g_hw[4*(size_t)DD*DD];     // weights in fp16
__device__ __half g_hnrm[(size_t)MM*DD];     // rmsnorm output in fp16

// ---------------------------------------------------------------------------
// helpers
// ---------------------------------------------------------------------------
__device__ __forceinline__ void mma_fp16(float c[4], const uint32_t a[4],
                                         uint32_t b0, uint32_t b1) {
    asm volatile(
        "mma.sync.aligned.m16n8k16.row.col.f32.f16.f16.f32 "
        "{%0,%1,%2,%3},{%4,%5,%6,%7},{%8,%9},{%0,%1,%2,%3};"
        : "+f"(c[0]), "+f"(c[1]), "+f"(c[2]), "+f"(c[3])
        : "r"(a[0]), "r"(a[1]), "r"(a[2]), "r"(a[3]), "r"(b0), "r"(b1));
}

__device__ __forceinline__ void ldm_x4(uint32_t r[4], uint32_t addr) {
    asm volatile(
        "ldmatrix.sync.aligned.m8n8.x4.shared.b16 {%0,%1,%2,%3}, [%4];"
        : "=r"(r[0]), "=r"(r[1]), "=r"(r[2]), "=r"(r[3]) : "r"(addr));
}

__device__ __forceinline__ void cp16(uint32_t dst, const void* src) {
    asm volatile("cp.async.cg.shared.global [%0], [%1], 16;"
                 :: "r"(dst), "l"(src));
}

__device__ __forceinline__ uint32_t s2u(const void* p) {
    uint32_t a;
    asm("{ .reg .u64 t; cvta.to.shared.u64 t, %1; cvt.u32.u64 %0, t; }"
        : "=r"(a) : "l"(p));
    return a;
}

// ---------------------------------------------------------------------------
// Pre-pass: fp32 -> fp16. Memory-bound.
// ---------------------------------------------------------------------------
__global__ __launch_bounds__(256)
void cvt_fp16_kernel(const float4* __restrict__ in, __half2* __restrict__ out,
                     int n4)
{
    int i = blockIdx.x * blockDim.x + threadIdx.x;
    if (i < n4) {
        float4 v = in[i];
        out[2*i]   = __floats2half2_rn(v.x, v.y);
        out[2*i+1] = __floats2half2_rn(v.z, v.w);
    }
}

// ---------------------------------------------------------------------------
// GEMM tile (device fn): C[bm:+128, bn:+128] = epi( A[M,K] @ W[Nc,K]^T ).
// BK=64 halves, 256 threads (8 warps 4x2), warp tile 32x64, ldmatrix.x4,
// cp.async 2-stage double buffer. mode: 0=SiLU, 1=KG, 2=identity.
// ---------------------------------------------------------------------------
#define RS 72
#define ABUF_BYTES (128 * RS * 2)
#define BREG_BYTES (2 * ABUF_BYTES)
#define GEMM_SMEM_BYTES (4 * ABUF_BYTES)   // 73728

__device__ __forceinline__
void gemm_tile(const __half* __restrict__ A, const __half* __restrict__ W,
               float* __restrict__ C, float* __restrict__ C2,
               int bm, int bn, int mode, uint32_t sb)
{
    const int K = DD, Nc = DD;
    const int t  = threadIdx.x;
    const int warp = t >> 5, lane = t & 31;
    const int wm = (warp >> 1) * 32;
    const int wn = (warp & 1) * 64;
    const int qrow = lane >> 2;
    const int qcol = lane & 3;

    float acc[2][8][4];
    #pragma unroll
    for (int mt = 0; mt < 2; mt++)
        #pragma unroll
        for (int nt = 0; nt < 8; nt++)
            #pragma unroll
            for (int i = 0; i < 4; i++) acc[mt][nt][i] = 0.f;

    int rowv[4], segv[4];
    #pragma unroll
    for (int r = 0; r < 4; r++) {
        int idx = t + r * 256;
        rowv[r] = idx >> 3;
        segv[r] = idx & 7;
    }

    const int lgrp = lane >> 3, lrow = lane & 7;
    uint32_t aoffb[2], boffb[4];
    #pragma unroll
    for (int mt = 0; mt < 2; mt++) {
        int row = wm + mt * 16 + (lgrp & 1) * 8 + lrow;
        aoffb[mt] = (uint32_t)(row * RS + (lgrp >> 1) * 8) * 2;
    }
    #pragma unroll
    for (int p = 0; p < 4; p++) {
        int row = wn + p * 16 + (lgrp >> 1) * 8 + lrow;
        boffb[p] = (uint32_t)(row * RS + (lgrp & 1) * 8) * 2 + BREG_BYTES;
    }

    #pragma unroll
    for (int r = 0; r < 4; r++) {
        uint32_t so = (uint32_t)(rowv[r] * RS + segv[r] * 8) * 2;
        cp16(sb + so,              &A[(size_t)(bm + rowv[r]) * K + segv[r] * 8]);
        cp16(sb + BREG_BYTES + so, &W[(size_t)(bn + rowv[r]) * K + segv[r] * 8]);
    }
    asm volatile("cp.async.commit_group;" ::: "memory");

    const int NCH = K / 64;
    #pragma unroll 1
    for (int ch = 0; ch < NCH; ch++) {
        const uint32_t bufB = (uint32_t)(ch & 1) * ABUF_BYTES;
        if (ch + 1 < NCH) {
            const uint32_t nbufB = (uint32_t)((ch + 1) & 1) * ABUF_BYTES;
            const int k0n = (ch + 1) * 64;
            #pragma unroll
            for (int r = 0; r < 4; r++) {
                uint32_t so = (uint32_t)(rowv[r] * RS + segv[r] * 8) * 2;
                cp16(sb + nbufB + so,
                     &A[(size_t)(bm + rowv[r]) * K + k0n + segv[r] * 8]);
                cp16(sb + BREG_BYTES + nbufB + so,
                     &W[(size_t)(bn + rowv[r]) * K + k0n + segv[r] * 8]);
            }
            asm volatile("cp.async.commit_group;" ::: "memory");
            asm volatile("cp.async.wait_group 1;" ::: "memory");
        } else {
            asm volatile("cp.async.wait_group 0;" ::: "memory");
        }
        __syncthreads();

        #pragma unroll
        for (int ks = 0; ks < 4; ks++) {
            const uint32_t kb = sb + bufB + (uint32_t)ks * 32;
            uint32_t a0[4], a1[4];
            ldm_x4(a0, kb + aoffb[0]);
            ldm_x4(a1, kb + aoffb[1]);
            #pragma unroll
            for (int p = 0; p < 4; p++) {
                uint32_t bb[4];
                ldm_x4(bb, kb + boffb[p]);
                mma_fp16(acc[0][2*p],   a0, bb[0], bb[1]);
                mma_fp16(acc[1][2*p],   a1, bb[0], bb[1]);
                mma_fp16(acc[0][2*p+1], a0, bb[2], bb[3]);
                mma_fp16(acc[1][2*p+1], a1, bb[2], bb[3]);
            }
        }
        __syncthreads();
    }

    #pragma unroll
    for (int mt = 0; mt < 2; mt++) {
        #pragma unroll
        for (int nt = 0; nt < 8; nt++) {
            int row = bm + wm + mt * 16 + qrow;
            int col = bn + wn + nt * 8 + qcol * 2;
            #pragma unroll
            for (int half = 0; half < 2; half++) {
                int r = row + half * 8;
                float z0 = acc[mt][nt][half * 2 + 0];
                float z1 = acc[mt][nt][half * 2 + 1];
                if (mode == 0) {
                    float s0 = 1.f / (1.f + __expf(-z0));
                    float s1 = 1.f / (1.f + __expf(-z1));
                    float2 o = make_float2(z0 * s0, z1 * s1);
                    *reinterpret_cast<float2*>(&C[(size_t)r * Nc + col]) = o;
                } else if (mode == 1) {
                    float f0 = 1.f / (1.f + __expf(-z0));
                    float f1 = 1.f / (1.f + __expf(-z1));
                    float2 kk2 = make_float2(1.f - f0, 1.f - f1);
                    float2 gg2 = make_float2(-log1pf(__expf(-f0)),
                                             -log1pf(__expf(-f1)));
                    *reinterpret_cast<float2*>(&C [(size_t)r * Nc + col]) = kk2;
                    *reinterpret_cast<float2*>(&C2[(size_t)r * Nc + col]) = gg2;
                } else {
                    float2 o = make_float2(z0, z1);
                    *reinterpret_cast<float2*>(&C[(size_t)r * Nc + col]) = o;
                }
            }
        }
    }
}

// ---------------------------------------------------------------------------
// Scan role: 256-thr CTA = 2 old 128-thr scan blocks (one per warp-quad).
// Warp-local staging + __syncwarp. TCH steps per launch; state in g_state.
// (Scan is natively time-chunked: per (b,h), t in [cs*TCH, (cs+1)*TCH).)
// ---------------------------------------------------------------------------
__device__ __forceinline__
void scan_role(int cta, int cs,
               const float* __restrict__ Q, const float* __restrict__ Kk,
               const float* __restrict__ G, const float* __restrict__ V,
               float* __restrict__ P0, float* __restrict__ P1,
               float* __restrict__ P2, float* __restrict__ P3,
               float* __restrict__ ST, float* smemf)
{
    float* sq = smemf;
    float* sk = smemf + 512;
    float* se = smemf + 1024;

    const int t = threadIdx.x;
    const int w = t >> 5, lane = t & 31;
    const int o = cta * 2 + (w >> 2);     // old block id 0..511
    const int bh  = o & 31;
    const int dvb = (o >> 5) & 3;
    const int dkb = o >> 7;
    const int b = bh >> 3, h = bh & 7;
    const int owid = w & 3;
    const int dv_local = owid * 8 + (lane >> 2);
    const int dkq = lane & 3;
    const int vcol = dvb * 32 + dv_local;
    const int tid128 = owid * 32 + lane;

    float* OP = (dkb == 0) ? P0 : (dkb == 1) ? P1 : (dkb == 2) ? P2 : P3;

    const size_t base = (size_t)b * NN * DD + (size_t)h * HDIM;

    float S[8];
    if (cs == 0) {
        #pragma unroll
        for (int i = 0; i < 8; i++) S[i] = 0.f;
    } else {
        #pragma unroll
        for (int i = 0; i < 8; i++)
            S[i] = ST[((size_t)o * 128 + tid128) * 8 + i];
    }

    size_t off = base + (size_t)(cs * TCH) * DD;
    float r0 = Q [off + dkb*32 + lane];
    float r1 = Kk[off + dkb*32 + lane];
    float r2 = G [off + dkb*32 + lane];
    float rv = V [off + vcol];

    #pragma unroll 1
    for (int tstep = 0; tstep < TCH; tstep++) {
        const int bi = (tstep & 1) * 256 + w * 32;
        sq[bi + lane] = r0;
        sk[bi + lane] = r1;
        se[bi + lane] = __expf(r2);
        const float vv = rv;

        const size_t noff = off + DD;
        if (tstep + 1 < TCH) {
            r0 = Q [noff + dkb*32 + lane];
            r1 = Kk[noff + dkb*32 + lane];
            r2 = G [noff + dkb*32 + lane];
            rv = V [noff + vcol];
        }
        __syncwarp();

        const float4* q4 = reinterpret_cast<const float4*>(sq + bi);
        const float4* k4 = reinterpret_cast<const float4*>(sk + bi);
        const float4* e4 = reinterpret_cast<const float4*>(se + bi);

        float oacc = 0.f;
        #pragma unroll
        for (int j = 0; j < 2; j++) {
            const int fi = dkq * 2 + j;
            float4 qa = q4[fi], ka = k4[fi], ea = e4[fi];
            float s;
            s = fmaf(ea.x, S[4*j+0], ka.x * vv); S[4*j+0] = s; oacc = fmaf(qa.x, s, oacc);
            s = fmaf(ea.y, S[4*j+1], ka.y * vv); S[4*j+1] = s; oacc = fmaf(qa.y, s, oacc);
            s = fmaf(ea.z, S[4*j+2], ka.z * vv); S[4*j+2] = s; oacc = fmaf(qa.z, s, oacc);
            s = fmaf(ea.w, S[4*j+3], ka.w * vv); S[4*j+3] = s; oacc = fmaf(qa.w, s, oacc);
        }
        oacc += __shfl_xor_sync(0xffffffffu, oacc, 1);
        oacc += __shfl_xor_sync(0xffffffffu, oacc, 2);
        if (dkq == 0) OP[off + vcol] = oacc;

        off = noff;
    }

    if (cs < 3) {
        #pragma unroll
        for (int i = 0; i < 8; i++)
            ST[((size_t)o * 128 + tid128) * 8 + i] = S[i];
    }
}

// ---------------------------------------------------------------------------
// RMSNorm role: 4 rows per 256-thr CTA. Time-chunk cr covers, for each b,
// rows b*NN + cr*TCH + [0,TCH). idx = cta*4+r in [0,2048):
//   b = idx>>9, row = b*NN + cr*TCH + (idx & 511).
// ---------------------------------------------------------------------------
__device__ __forceinline__
void rms_role(int cta, int cr,
              const float* __restrict__ X0, const float* __restrict__ X1,
              const float* __restrict__ X2, const float* __restrict__ X3,
              const float* __restrict__ w, __half2* __restrict__ Y,
              float* smemf)
{
    float* red = smemf;   // 8 floats
    const int t = threadIdx.x;

    #pragma unroll 1
    for (int r = 0; r < 4; r++) {
        const int ci  = cta * 4 + r;                      // 0..2047
        const int row = (ci >> 9) * NN + cr * TCH + (ci & 511);
        const size_t idx = (size_t)row * DD + t * 4;

        float4 a  = *reinterpret_cast<const float4*>(&X0[idx]);
        float4 bq = *reinterpret_cast<const float4*>(&X1[idx]);
        float4 c  = *reinterpret_cast<const float4*>(&X2[idx]);
        float4 d  = *reinterpret_cast<const float4*>(&X3[idx]);
        float4 xv;
        xv.x = (a.x + bq.x) + (c.x + d.x);
        xv.y = (a.y + bq.y) + (c.y + d.y);
        xv.z = (a.z + bq.z) + (c.z + d.z);
        xv.w = (a.w + bq.w) + (c.w + d.w);

        float ss = xv.x*xv.x + xv.y*xv.y + xv.z*xv.z + xv.w*xv.w;
        #pragma unroll
        for (int o = 16; o; o >>= 1) ss += __shfl_xor_sync(0xffffffffu, ss, o);
        if ((t & 31) == 0) red[t >> 5] = ss;
        __syncthreads();
        if (t < 8) {
            float x = red[t];
            #pragma unroll
            for (int o = 4; o; o >>= 1) x += __shfl_xor_sync(0xffu, x, o);
            if (t == 0) red[0] = x;
        }
        __syncthreads();
        float inv = rsqrtf(red[0] * (1.f / DD) + 1e-6f);

        float4 wv = *reinterpret_cast<const float4*>(&w[t * 4]);
        size_t o2 = (size_t)row * (DD/2) + t * 2;
        Y[o2]   = __floats2half2_rn(xv.x * inv * wv.x, xv.y * inv * wv.y);
        Y[o2+1] = __floats2half2_rn(xv.z * inv * wv.z, xv.w * inv * wv.w);
        __syncthreads();
    }
}

// ---------------------------------------------------------------------------
// Time-chunk GEMM m-tile mapping: tile mt in 0..15 covers, within chunk c,
// rows (mt>>2)*NN + c*TCH + (mt&3)*128 .. +128 (contiguous, same batch).
// ---------------------------------------------------------------------------
__device__ __forceinline__ int chunk_bm(int c, int mt) {
    return (mt >> 2) * NN + c * TCH + (mt & 3) * 128;
}

// ---------------------------------------------------------------------------
// Mega kernel: heterogeneous roles by blockIdx range.
// Grid layout: [scan | rms | O-tiles | QKV-tiles]
// ---------------------------------------------------------------------------
__global__ __launch_bounds__(256, 2)
void mega_kernel(const __half* __restrict__ hx, const __half* __restrict__ hw,
                 float* __restrict__ pq, float* __restrict__ pk,
                 float* __restrict__ pg, float* __restrict__ pv,
                 float* __restrict__ p0, float* __restrict__ p1,
                 float* __restrict__ p2, float* __restrict__ p3,
                 float* __restrict__ pstate, __half* __restrict__ hnrm,
                 const float* __restrict__ norm_w, float* __restrict__ outp,
                 int n_scan, int cs, int n_rms, int cr,
                 int n_o, int co, int cq)
{
    extern __shared__ __align__(16) __half smem_raw[];
    int bid = blockIdx.x;

    if (bid < n_scan) {
        scan_role(bid, cs, pq, pk, pg, pv, p0, p1, p2, p3, pstate,
                  reinterpret_cast<float*>(smem_raw));
        return;
    }
    bid -= n_scan;
    if (bid < n_rms) {
        rms_role(bid, cr, p0, p1, p2, p3, norm_w,
                 reinterpret_cast<__half2*>(hnrm),
                 reinterpret_cast<float*>(smem_raw));
        return;
    }
    bid -= n_rms;
    const uint32_t sb = s2u(smem_raw);
    if (bid < n_o) {
        int mt = bid >> 3, nt = bid & 7;
        gemm_tile(hnrm, hw + 3*(size_t)DD*DD, outp, nullptr,
                  chunk_bm(co, mt), nt * 128, 2, sb);
        return;
    }
    bid -= n_o;
    // QKV tiles: 384 per chunk (3 GEMMs x 16 m-tiles x 8 n-tiles)
    int which = bid / 128;
    int tile  = bid % 128;
    int mt = tile >> 3, nt = tile & 7;
    const __half* Wp = hw + (size_t)which * DD * DD;
    float* C  = (which == 0) ? pq : (which == 1) ? pk : pv;
    float* C2 = (which == 1) ? pg : nullptr;
    gemm_tile(hx, Wp, C, C2, chunk_bm(cq, mt), nt * 128, which, sb);
}

// ---------------------------------------------------------------------------
extern "C" void kernel_launch(void* const* d_in, const int* in_sizes, int n_in,
                              void* d_out, int out_size)
{
    const float* x      = (const float*)d_in[0];
    const float* Wq     = (const float*)d_in[1];
    const float* Wk     = (const float*)d_in[2];
    const float* Wv     = (const float*)d_in[3];
    const float* Wo     = (const float*)d_in[4];
    const float* norm_w = (const float*)d_in[5];
    float* out = (float*)d_out;

    float *pq, *pk, *pg, *pv, *p0, *p1, *p2, *p3, *pstate;
    __half *phx, *phw, *phnrm;
    cudaGetSymbolAddress((void**)&pq,     g_q);
    cudaGetSymbolAddress((void**)&pk,     g_k);
    cudaGetSymbolAddress((void**)&pg,     g_g);
    cudaGetSymbolAddress((void**)&pv,     g_v);
    cudaGetSymbolAddress((void**)&p0,     g_p0);
    cudaGetSymbolAddress((void**)&p1,     g_p1);
    cudaGetSymbolAddress((void**)&p2,     g_p2);
    cudaGetSymbolAddress((void**)&p3,     g_p3);
    cudaGetSymbolAddress((void**)&pstate, g_state);
    cudaGetSymbolAddress((void**)&phx,    g_hx);
    cudaGetSymbolAddress((void**)&phw,    g_hw);
    cudaGetSymbolAddress((void**)&phnrm,  g_hnrm);

    // Pre-pass: fp32 -> fp16 for x and weights (Wq,Wk,Wv,Wo packed in g_hw)
    const int n4x = MM * DD / 4;
    const int n4w = DD * DD / 4;
    cvt_fp16_kernel<<<(n4x + 255) / 256, 256>>>((const float4*)x,  (__half2*)phx, n4x);
    cvt_fp16_kernel<<<(n4w + 255) / 256, 256>>>((const float4*)Wq, (__half2*)(phw),                    n4w);
    cvt_fp16_kernel<<<(n4w + 255) / 256, 256>>>((const float4*)Wk, (__half2*)(phw +   (size_t)DD*DD), n4w);
    cvt_fp16_kernel<<<(n4w + 255) / 256, 256>>>((const float4*)Wv, (__half2*)(phw + 2*(size_t)DD*DD), n4w);
    cvt_fp16_kernel<<<(n4w + 255) / 256, 256>>>((const float4*)Wo, (__half2*)(phw + 3*(size_t)DD*DD), n4w);

    cudaFuncSetAttribute(mega_kernel,
        cudaFuncAttributeMaxDynamicSharedMemorySize, GEMM_SMEM_BYTES);

    #define LAUNCH(nsc, csv, nrm, crv, no, cov, nqkv, cqv)                        \
        mega_kernel<<<(nsc)+(nrm)+(no)+(nqkv), 256, GEMM_SMEM_BYTES>>>(           \
            phx, phw, pq, pk, pg, pv, p0, p1, p2, p3, pstate, phnrm,              \
            norm_w, out, (nsc), (csv), (nrm), (crv), (no), (cov), (cqv))

    // Pipeline: scan(k-1) / rms(k-2) / O(k-3) overlap QKV(k)
    LAUNCH(  0, 0,   0, 0,   0, 0, 384, 0);   // L0: QKV(0)
    LAUNCH(256, 0,   0, 0,   0, 0, 384, 1);   // L1: scan(0) + QKV(1)
    LAUNCH(256, 1, 512, 0,   0, 0, 384, 2);   // L2: scan(1)+rms(0)+QKV(2)
    LAUNCH(256, 2, 512, 1, 128, 0, 384, 3);   // L3: scan(2)+rms(1)+O(0)+QKV(3)
    LAUNCH(256, 3, 512, 2, 128, 1,   0, 0);   // L4: scan(3)+rms(2)+O(1)
    LAUNCH(  0, 0, 512, 3, 128, 2,   0, 0);   // L5: rms(3)+O(2)
    LAUNCH(  0, 0,   0, 0, 128, 3,   0, 0);   // L6: O(3)
    #undef LAUNCH
}